// round 6
// baseline (speedup 1.0000x reference)
#include <cuda_runtime.h>
#include <cuda_bf16.h>
#include <cstdint>
#include <math.h>

#define BATCH 4
#define SEQ   2048
#define DMODEL 1024
#define NH    8
#define HD    128
#define HDIM  1024

// ---------------------------------------------------------------------------
// Scratch (device globals: allocation-free rule)
// ---------------------------------------------------------------------------
__device__ float g_qkv[(size_t)BATCH * SEQ * 3 * HDIM];          // [B,T,3*HDIM]
__device__ float g_v[(size_t)BATCH * NH * SEQ * HD];             // [B,H,T,D] fp32
__device__ __nv_bfloat16 g_qh[(size_t)BATCH * NH * SEQ * HD];    // [B,H,T,D]
__device__ __nv_bfloat16 g_ql[(size_t)BATCH * NH * SEQ * HD];
__device__ __nv_bfloat16 g_kh[(size_t)BATCH * NH * SEQ * HD];
__device__ __nv_bfloat16 g_kl[(size_t)BATCH * NH * SEQ * HD];
__device__ __nv_bfloat16 g_vh[(size_t)BATCH * NH * HD * SEQ];    // [B,H,D,T]
__device__ __nv_bfloat16 g_vl[(size_t)BATCH * NH * HD * SEQ];
// pre-split GEMM operands
__device__ __nv_bfloat16 g_xh[(size_t)BATCH * SEQ * DMODEL];
__device__ __nv_bfloat16 g_xl[(size_t)BATCH * SEQ * DMODEL];
__device__ __nv_bfloat16 g_wqh[(size_t)3 * HDIM * DMODEL];
__device__ __nv_bfloat16 g_wql[(size_t)3 * HDIM * DMODEL];
__device__ __nv_bfloat16 g_wph[(size_t)DMODEL * HDIM];
__device__ __nv_bfloat16 g_wpl[(size_t)DMODEL * HDIM];
__device__ __nv_bfloat16 g_yh[(size_t)BATCH * SEQ * HDIM];       // flash out (split)
__device__ __nv_bfloat16 g_yl[(size_t)BATCH * SEQ * HDIM];

// ---------------------------------------------------------------------------
// PTX helpers
// ---------------------------------------------------------------------------
__device__ __forceinline__ uint32_t smem_u32(const void* p) {
    uint32_t a;
    asm("{ .reg .u64 t; cvta.to.shared.u64 t, %1; cvt.u32.u64 %0, t; }"
        : "=r"(a) : "l"(p));
    return a;
}

#define LDMX4(r, addr) \
    asm volatile("ldmatrix.sync.aligned.m8n8.x4.shared.b16 {%0,%1,%2,%3}, [%4];" \
        : "=r"((r)[0]), "=r"((r)[1]), "=r"((r)[2]), "=r"((r)[3]) : "r"(addr))

#define MMA_BF16(d, a, b0, b1) \
    asm volatile("mma.sync.aligned.m16n8k16.row.col.f32.bf16.bf16.f32 " \
        "{%0,%1,%2,%3},{%4,%5,%6,%7},{%8,%9},{%0,%1,%2,%3};" \
        : "+f"((d)[0]), "+f"((d)[1]), "+f"((d)[2]), "+f"((d)[3]) \
        : "r"((a)[0]), "r"((a)[1]), "r"((a)[2]), "r"((a)[3]), "r"(b0), "r"(b1))

#define CP_ASYNC16(dst, src) \
    asm volatile("cp.async.cg.shared.global [%0], [%1], 16;" :: "r"(dst), "l"(src) : "memory")
#define CP_COMMIT() asm volatile("cp.async.commit_group;" ::: "memory")
#define CP_WAIT0()  asm volatile("cp.async.wait_group 0;" ::: "memory")
#define CP_WAIT1()  asm volatile("cp.async.wait_group 1;" ::: "memory")

__device__ __forceinline__ uint32_t packbf(float e0, float e1) {
    uint32_t d;
    asm("cvt.rn.bf16x2.f32 %0, %1, %2;" : "=r"(d) : "f"(e1), "f"(e0));
    return d;
}
__device__ __forceinline__ float bfx2_lo(uint32_t p) { return __uint_as_float(p << 16); }
__device__ __forceinline__ float bfx2_hi(uint32_t p) { return __uint_as_float(p & 0xFFFF0000u); }

// ---------------------------------------------------------------------------
// split: fp32 -> bf16 hi/lo
// ---------------------------------------------------------------------------
__global__ __launch_bounds__(256) void split_kernel(
    const float* __restrict__ src, __nv_bfloat16* __restrict__ hi,
    __nv_bfloat16* __restrict__ lo, int n4)
{
    int i = blockIdx.x * 256 + threadIdx.x;
    if (i < n4) {
        float4 v = ((const float4*)src)[i];
        uint32_t h0 = packbf(v.x, v.y), h1 = packbf(v.z, v.w);
        uint32_t l0 = packbf(v.x - bfx2_lo(h0), v.y - bfx2_hi(h0));
        uint32_t l1 = packbf(v.z - bfx2_lo(h1), v.w - bfx2_hi(h1));
        ((uint2*)hi)[i] = make_uint2(h0, h1);
        ((uint2*)lo)[i] = make_uint2(l0, l1);
    }
}

// ===========================================================================
// bf16-split GEMM, term-major MMA order (RAW distance 16 between same-acc
// MMAs). CTA 256x128, 512 threads, 3-stage cp.async.
// ===========================================================================
#define GA_PART  20480
#define GB_PART  10240
#define G_STAGE  (2 * GA_PART + 2 * GB_PART)      // 61440
#define G_SMEM   (3 * G_STAGE)                    // 184320

__global__ __launch_bounds__(512, 1) void gemm_bf16s(
    const __nv_bfloat16* __restrict__ Ah, const __nv_bfloat16* __restrict__ Al,
    const __nv_bfloat16* __restrict__ Bh, const __nv_bfloat16* __restrict__ Bl,
    float* __restrict__ C, int Kd, int Nd)
{
    extern __shared__ char smem[];
    const uint32_t sb = smem_u32(smem);
    const int tid = threadIdx.x;
    const int wid = tid >> 5, lane = tid & 31;
    const int wm = wid >> 2, wn = wid & 3;        // 4x4 warp grid
    const int m0 = blockIdx.y * 256, n0 = blockIdx.x * 128;
    const int nch = Kd / 32;

    auto load_stage = [&](int c) {
        const uint32_t st = sb + (c % 3) * G_STAGE;
        const __nv_bfloat16* pAh = Ah + (size_t)m0 * Kd + c * 32;
        const __nv_bfloat16* pAl = Al + (size_t)m0 * Kd + c * 32;
        const __nv_bfloat16* pBh = Bh + (size_t)n0 * Kd + c * 32;
        const __nv_bfloat16* pBl = Bl + (size_t)n0 * Kd + c * 32;
#pragma unroll
        for (int i = 0; i < 2; i++) {
            const int cc = i * 512 + tid;
            const int row = cc >> 2, col = cc & 3;
            const uint32_t off = row * 80 + col * 16;
            const size_t gi = (size_t)row * Kd + col * 8;
            CP_ASYNC16(st + off,           pAh + gi);
            CP_ASYNC16(st + GA_PART + off, pAl + gi);
        }
        {
            const int row = tid >> 2, col = tid & 3;
            const uint32_t off = row * 80 + col * 16;
            const size_t gi = (size_t)row * Kd + col * 8;
            CP_ASYNC16(st + 2 * GA_PART + off,           pBh + gi);
            CP_ASYNC16(st + 2 * GA_PART + GB_PART + off, pBl + gi);
        }
    };

    float acc[4][4][4];
#pragma unroll
    for (int i = 0; i < 4; i++)
#pragma unroll
        for (int j = 0; j < 4; j++)
#pragma unroll
            for (int e = 0; e < 4; e++) acc[i][j][e] = 0.f;

    auto compute = [&](int s) {
        const uint32_t st = sb + s * G_STAGE;
        const uint32_t lrow = (lane & 15);
        const uint32_t lcol = (lane >> 4) * 16;
#pragma unroll
        for (int k16 = 0; k16 < 2; k16++) {
            const uint32_t kb2 = k16 * 32;
            uint32_t ah[4][4], al[4][4];
#pragma unroll
            for (int i = 0; i < 4; i++) {
                uint32_t aaddr = st + (wm * 64 + i * 16 + lrow) * 80 + kb2 + lcol;
                LDMX4(ah[i], aaddr);
                LDMX4(al[i], aaddr + GA_PART);
            }
            uint32_t bh_[4][2], bl_[4][2];
#pragma unroll
            for (int jj = 0; jj < 2; jj++) {
                uint32_t r[4];
                uint32_t baddr = st + 2 * GA_PART + (wn * 32 + jj * 16 + lrow) * 80 + kb2 + lcol;
                LDMX4(r, baddr);
                bh_[2 * jj][0] = r[0]; bh_[2 * jj][1] = r[2];
                bh_[2 * jj + 1][0] = r[1]; bh_[2 * jj + 1][1] = r[3];
                LDMX4(r, baddr + GB_PART);
                bl_[2 * jj][0] = r[0]; bl_[2 * jj][1] = r[2];
                bl_[2 * jj + 1][0] = r[1]; bl_[2 * jj + 1][1] = r[3];
            }
            // term-major: consecutive MMAs hit different accumulators
#pragma unroll
            for (int i = 0; i < 4; i++)
#pragma unroll
                for (int j = 0; j < 4; j++)
                    MMA_BF16(acc[i][j], ah[i], bh_[j][0], bh_[j][1]);
#pragma unroll
            for (int i = 0; i < 4; i++)
#pragma unroll
                for (int j = 0; j < 4; j++)
                    MMA_BF16(acc[i][j], al[i], bh_[j][0], bh_[j][1]);
#pragma unroll
            for (int i = 0; i < 4; i++)
#pragma unroll
                for (int j = 0; j < 4; j++)
                    MMA_BF16(acc[i][j], ah[i], bl_[j][0], bl_[j][1]);
        }
    };

    load_stage(0); CP_COMMIT();
    if (nch > 1) { load_stage(1); CP_COMMIT(); }
    for (int c = 0; c < nch; c++) {
        if (c + 1 < nch) CP_WAIT1(); else CP_WAIT0();
        __syncthreads();
        if (c + 2 < nch) { load_stage(c + 2); CP_COMMIT(); }
        compute(c % 3);
    }

    // ---- epilogue ----
    const int r = lane >> 2;
    const int cb = (lane & 3) * 2;
#pragma unroll
    for (int i = 0; i < 4; i++) {
        const int row0 = m0 + wm * 64 + i * 16 + r;
#pragma unroll
        for (int j = 0; j < 4; j++) {
            const int col = n0 + wn * 32 + j * 8 + cb;
            *(float2*)(C + (size_t)row0 * Nd + col) = make_float2(acc[i][j][0], acc[i][j][1]);
            *(float2*)(C + (size_t)(row0 + 8) * Nd + col) = make_float2(acc[i][j][2], acc[i][j][3]);
        }
    }
}

// ---------------------------------------------------------------------------
// prep: per (b,t,h) RMS-norm q,k; RoPE; v-mix.
// ---------------------------------------------------------------------------
__global__ __launch_bounds__(128) void prep_kernel(
    const float* __restrict__ qkv, const float* __restrict__ ve,
    const float* __restrict__ lam,
    __nv_bfloat16* __restrict__ Qh, __nv_bfloat16* __restrict__ Ql,
    __nv_bfloat16* __restrict__ Kh, __nv_bfloat16* __restrict__ Kl,
    float* __restrict__ V)
{
    const int idx = blockIdx.x;
    const int h = idx % NH;
    const int bt = idx / NH;
    const int t = bt % SEQ;
    const int b = bt / SEQ;
    const int d = threadIdx.x;

    const float* base = qkv + (size_t)bt * 3 * HDIM;
    float qv = base[h * HD + d];
    float kv = base[HDIM + h * HD + d];
    float vv = base[2 * HDIM + h * HD + d];

    float sq = qv * qv, sk = kv * kv;
#pragma unroll
    for (int o = 16; o; o >>= 1) {
        sq += __shfl_xor_sync(0xffffffffu, sq, o);
        sk += __shfl_xor_sync(0xffffffffu, sk, o);
    }
    __shared__ float wq[4], wk[4];
    if ((d & 31) == 0) { wq[d >> 5] = sq; wk[d >> 5] = sk; }
    __syncthreads();
    float tq = (wq[0] + wq[1]) + (wq[2] + wq[3]);
    float tk = (wk[0] + wk[1]) + (wk[2] + wk[3]);
    const float EPS = 1.1920929e-7f;
    float rq = rsqrtf(tq * (1.0f / 128.0f) + EPS);
    float rk = rsqrtf(tk * (1.0f / 128.0f) + EPS);

    __shared__ float nq[128], nk[128];
    nq[d] = qv * rq;
    nk[d] = kv * rk;
    __syncthreads();

    const int i = d & 63;
    float c, s;
    if (i < 32) {
        float xi = (float)i / 31.0f;
        float f = (float)exp2(-10.0 * (double)xi);
        float th = (float)t * f;
        c = cosf(th);
        s = sinf(th);
    } else {
        c = 1.0f; s = 0.0f;
    }
    float qo, ko;
    if (d < 64) { qo = nq[d] * c + nq[d + 64] * s; ko = nk[d] * c + nk[d + 64] * s; }
    else        { qo = nq[d] * c - nq[d - 64] * s; ko = nk[d] * c - nk[d - 64] * s; }

    float vo = lam[0] * vv + lam[1] * ve[(size_t)bt * HDIM + h * HD + d];

    size_t o = ((size_t)(b * NH + h) * SEQ + t) * HD + d;
    __nv_bfloat16 qhi = __float2bfloat16(qo);
    __nv_bfloat16 khi = __float2bfloat16(ko);
    Qh[o] = qhi; Ql[o] = __float2bfloat16(qo - __bfloat162float(qhi));
    Kh[o] = khi; Kl[o] = __float2bfloat16(ko - __bfloat162float(khi));
    V[o] = vo;
}

// ---------------------------------------------------------------------------
// vtrans: V [BH][T][D] fp32 -> Vh/Vl [BH][D][T] bf16 split
// ---------------------------------------------------------------------------
__global__ __launch_bounds__(256) void vtrans_kernel(
    const float* __restrict__ V,
    __nv_bfloat16* __restrict__ Vh, __nv_bfloat16* __restrict__ Vl)
{
    __shared__ float tile[32][33];
    const int bh = blockIdx.z;
    const int t0 = blockIdx.x * 32, d0 = blockIdx.y * 32;
    const int tx = threadIdx.x & 31, ty = threadIdx.x >> 5;
    const float* src = V + (size_t)bh * SEQ * HD;
#pragma unroll
    for (int i = 0; i < 4; i++)
        tile[ty + i * 8][tx] = src[(size_t)(t0 + ty + i * 8) * HD + d0 + tx];
    __syncthreads();
    __nv_bfloat16* dh = Vh + (size_t)bh * HD * SEQ;
    __nv_bfloat16* dl = Vl + (size_t)bh * HD * SEQ;
#pragma unroll
    for (int i = 0; i < 4; i++) {
        float v = tile[tx][ty + i * 8];
        __nv_bfloat16 hi = __float2bfloat16(v);
        size_t o = (size_t)(d0 + ty + i * 8) * SEQ + t0 + tx;
        dh[o] = hi;
        dl[o] = __float2bfloat16(v - __bfloat162float(hi));
    }
}

// ===========================================================================
// Flash attention, bf16-split mma, dependency-distance-optimized MMA order.
// ===========================================================================
#define FQ_PART 34816
#define FK_PART 17408
#define FV_PART 18432
#define FSTAGE  (2 * FK_PART + 2 * FV_PART)
#define FSTAGE0 (2 * FQ_PART)
#define F_SMEM  (FSTAGE0 + 2 * FSTAGE)

__global__ __launch_bounds__(256, 1) void flash_mma(
    const __nv_bfloat16* __restrict__ Qh, const __nv_bfloat16* __restrict__ Ql,
    const __nv_bfloat16* __restrict__ Kh, const __nv_bfloat16* __restrict__ Kl,
    const __nv_bfloat16* __restrict__ Vh, const __nv_bfloat16* __restrict__ Vl,
    __nv_bfloat16* __restrict__ Yh, __nv_bfloat16* __restrict__ Yl)
{
    extern __shared__ char smem[];
    const uint32_t sbase = smem_u32(smem);
    const int tid = threadIdx.x;
    const int wid = tid >> 5, lane = tid & 31;
    const int qt = gridDim.x - 1 - blockIdx.x;
    const int bh = blockIdx.y;
    const int b = bh >> 3, h = bh & 7;

    const size_t TD = (size_t)SEQ * HD;
    const __nv_bfloat16* qh_b = Qh + bh * TD;
    const __nv_bfloat16* ql_b = Ql + bh * TD;
    const __nv_bfloat16* kh_b = Kh + bh * TD;
    const __nv_bfloat16* kl_b = Kl + bh * TD;
    const __nv_bfloat16* vh_b = Vh + bh * TD;
    const __nv_bfloat16* vl_b = Vl + bh * TD;

#pragma unroll
    for (int i = 0; i < 16; i++) {
        int c = i * 256 + tid;
        int part = c >> 11;
        int c2 = c & 2047;
        int row = c2 >> 4, col = c2 & 15;
        uint32_t dst = sbase + part * FQ_PART + row * 272 + col * 16;
        const __nv_bfloat16* src = (part ? ql_b : qh_b) + (size_t)(qt * 128 + row) * 128 + col * 8;
        CP_ASYNC16(dst, src);
    }
    auto load_kv = [&](int kt, int s) {
        uint32_t kb = sbase + FSTAGE0 + s * FSTAGE;
#pragma unroll
        for (int i = 0; i < 4; i++) {
            int c = i * 256 + tid;
            int row = c >> 4, col = c & 15;
            uint32_t off = row * 272 + col * 16;
            size_t gi = (size_t)(kt * 64 + row) * 128 + col * 8;
            CP_ASYNC16(kb + off, kh_b + gi);
            CP_ASYNC16(kb + FK_PART + off, kl_b + gi);
        }
#pragma unroll
        for (int i = 0; i < 4; i++) {
            int c = i * 256 + tid;
            int row = c >> 3, col = c & 7;
            uint32_t off = row * 144 + col * 16;
            size_t gi = (size_t)row * SEQ + kt * 64 + col * 8;
            CP_ASYNC16(kb + 2 * FK_PART + off, vh_b + gi);
            CP_ASYNC16(kb + 2 * FK_PART + FV_PART + off, vl_b + gi);
        }
    };
    load_kv(0, 0);
    CP_COMMIT();

    float acc[16][4];
#pragma unroll
    for (int i = 0; i < 16; i++)
#pragma unroll
        for (int e = 0; e < 4; e++) acc[i][e] = 0.f;
    float m_i[2] = {-1e30f, -1e30f};
    float l_i[2] = {0.f, 0.f};

    const uint32_t lrow = lane & 15;
    const uint32_t lcol = (lane >> 4) * 16;
    const int nkt = 2 * qt + 2;
    const float SC = 0.08838834764831845f;

    for (int kt = 0; kt < nkt; kt++) {
        if (kt + 1 < nkt) {
            load_kv(kt + 1, (kt + 1) & 1);
            CP_COMMIT();
            CP_WAIT1();
        } else {
            CP_WAIT0();
        }
        __syncthreads();
        const uint32_t kb = sbase + FSTAGE0 + (kt & 1) * FSTAGE;

        // ---------- S = Q @ K^T (term-major; RAW distance 8) ----------
        float s[8][4];
#pragma unroll
        for (int j = 0; j < 8; j++)
#pragma unroll
            for (int e = 0; e < 4; e++) s[j][e] = 0.f;

        const uint32_t qrow = sbase + (wid * 16 + lrow) * 272 + lcol;
#pragma unroll
        for (int k16 = 0; k16 < 8; k16++) {
            uint32_t qa = qrow + k16 * 32;
            uint32_t ah[4], al[4];
            LDMX4(ah, qa);
            LDMX4(al, qa + FQ_PART);
            uint32_t khf[4][4], klf[4][4];
#pragma unroll
            for (int jj = 0; jj < 4; jj++) {
                uint32_t ka = kb + (jj * 16 + lrow) * 272 + lcol + k16 * 32;
                LDMX4(khf[jj], ka);
                LDMX4(klf[jj], ka + FK_PART);
            }
#pragma unroll
            for (int jj = 0; jj < 4; jj++) {
                MMA_BF16(s[2 * jj], ah, khf[jj][0], khf[jj][2]);
                MMA_BF16(s[2 * jj + 1], ah, khf[jj][1], khf[jj][3]);
            }
#pragma unroll
            for (int jj = 0; jj < 4; jj++) {
                MMA_BF16(s[2 * jj], al, khf[jj][0], khf[jj][2]);
                MMA_BF16(s[2 * jj + 1], al, khf[jj][1], khf[jj][3]);
            }
#pragma unroll
            for (int jj = 0; jj < 4; jj++) {
                MMA_BF16(s[2 * jj], ah, klf[jj][0], klf[jj][2]);
                MMA_BF16(s[2 * jj + 1], ah, klf[jj][1], klf[jj][3]);
            }
        }

        const bool need_mask = (kt >= 2 * qt);
#pragma unroll
        for (int hh = 0; hh < 2; hh++) {
            const int rowg = qt * 128 + wid * 16 + (lane >> 2) + hh * 8;
            float mt = -1e30f;
#pragma unroll
            for (int j = 0; j < 8; j++) {
#pragma unroll
                for (int e = 0; e < 2; e++) {
                    float v = s[j][2 * hh + e] * SC;
                    if (need_mask) {
                        int colg = kt * 64 + j * 8 + (lane & 3) * 2 + e;
                        if (colg > rowg) v = -1e30f;
                    }
                    s[j][2 * hh + e] = v;
                    mt = fmaxf(mt, v);
                }
            }
            mt = fmaxf(mt, __shfl_xor_sync(0xffffffffu, mt, 1));
            mt = fmaxf(mt, __shfl_xor_sync(0xffffffffu, mt, 2));
            float mn = fmaxf(m_i[hh], mt);
            float corr = __expf(m_i[hh] - mn);
            m_i[hh] = mn;
            float rs = 0.f;
#pragma unroll
            for (int j = 0; j < 8; j++) {
#pragma unroll
                for (int e = 0; e < 2; e++) {
                    float p = __expf(s[j][2 * hh + e] - mn);
                    s[j][2 * hh + e] = p;
                    rs += p;
                }
            }
            rs += __shfl_xor_sync(0xffffffffu, rs, 1);
            rs += __shfl_xor_sync(0xffffffffu, rs, 2);
            l_i[hh] = l_i[hh] * corr + rs;
#pragma unroll
            for (int ot = 0; ot < 16; ot++) {
                acc[ot][2 * hh] *= corr;
                acc[ot][2 * hh + 1] *= corr;
            }
        }

        // ---------- acc += P @ V (paired rows; RAW distance 4) ----------
        const uint32_t vb = kb + 2 * FK_PART;
#pragma unroll
        for (int kk = 0; kk < 4; kk++) {
            const int j0 = 2 * kk, j1 = 2 * kk + 1;
            uint32_t ahp[4], alp[4];
            ahp[0] = packbf(s[j0][0], s[j0][1]);
            ahp[1] = packbf(s[j0][2], s[j0][3]);
            ahp[2] = packbf(s[j1][0], s[j1][1]);
            ahp[3] = packbf(s[j1][2], s[j1][3]);
            alp[0] = packbf(s[j0][0] - bfx2_lo(ahp[0]), s[j0][1] - bfx2_hi(ahp[0]));
            alp[1] = packbf(s[j0][2] - bfx2_lo(ahp[1]), s[j0][3] - bfx2_hi(ahp[1]));
            alp[2] = packbf(s[j1][0] - bfx2_lo(ahp[2]), s[j1][1] - bfx2_hi(ahp[2]));
            alp[3] = packbf(s[j1][2] - bfx2_lo(ahp[3]), s[j1][3] - bfx2_hi(ahp[3]));
#pragma unroll
            for (int jp = 0; jp < 4; jp++) {
                const int ja = 2 * jp, jb = 2 * jp + 1;
                uint32_t rA[4], rB[4];
                uint32_t vaA = vb + (ja * 16 + lrow) * 144 + kk * 32 + lcol;
                uint32_t vaB = vb + (jb * 16 + lrow) * 144 + kk * 32 + lcol;
                LDMX4(rA, vaA);
                LDMX4(rB, vaB);
                MMA_BF16(acc[2 * ja], ahp, rA[0], rA[2]);
                MMA_BF16(acc[2 * ja + 1], ahp, rA[1], rA[3]);
                MMA_BF16(acc[2 * jb], ahp, rB[0], rB[2]);
                MMA_BF16(acc[2 * jb + 1], ahp, rB[1], rB[3]);
                MMA_BF16(acc[2 * ja], alp, rA[0], rA[2]);
                MMA_BF16(acc[2 * ja + 1], alp, rA[1], rA[3]);
                MMA_BF16(acc[2 * jb], alp, rB[0], rB[2]);
                MMA_BF16(acc[2 * jb + 1], alp, rB[1], rB[3]);
                LDMX4(rA, vaA + FV_PART);
                LDMX4(rB, vaB + FV_PART);
                MMA_BF16(acc[2 * ja], ahp, rA[0], rA[2]);
                MMA_BF16(acc[2 * ja + 1], ahp, rA[1], rA[3]);
                MMA_BF16(acc[2 * jb], ahp, rB[0], rB[2]);
                MMA_BF16(acc[2 * jb + 1], ahp, rB[1], rB[3]);
            }
        }
        __syncthreads();
    }

    // ---------- epilogue: write pre-split bf16 Y ----------
    const float inv0 = 1.f / l_i[0];
    const float inv1 = 1.f / l_i[1];
    const int r0 = qt * 128 + wid * 16 + (lane >> 2);
    const int cb = (lane & 3) * 2;
#pragma unroll
    for (int ot = 0; ot < 16; ot++) {
        const int d = ot * 8 + cb;
        size_t o0 = ((size_t)b * SEQ + r0) * HDIM + h * HD + d;
        size_t o1 = o0 + (size_t)8 * HDIM;
        float a0 = acc[ot][0] * inv0, a1 = acc[ot][1] * inv0;
        float a2 = acc[ot][2] * inv1, a3 = acc[ot][3] * inv1;
        uint32_t h0 = packbf(a0, a1);
        uint32_t l0 = packbf(a0 - bfx2_lo(h0), a1 - bfx2_hi(h0));
        uint32_t h1 = packbf(a2, a3);
        uint32_t l1 = packbf(a2 - bfx2_lo(h1), a3 - bfx2_hi(h1));
        *(uint32_t*)(Yh + o0) = h0;
        *(uint32_t*)(Yl + o0) = l0;
        *(uint32_t*)(Yh + o1) = h1;
        *(uint32_t*)(Yl + o1) = l1;
    }
}

// ---------------------------------------------------------------------------
extern "C" void kernel_launch(void* const* d_in, const int* in_sizes, int n_in,
                              void* d_out, int out_size)
{
    const float* x        = (const float*)d_in[0];
    const float* ve       = (const float*)d_in[1];
    const float* qkv_w    = (const float*)d_in[2];   // [3*HDIM, DIM]
    const float* lambdas  = (const float*)d_in[3];
    const float* c_proj_w = (const float*)d_in[4];   // [DIM, HDIM]
    float* out = (float*)d_out;

    float *qkv, *V;
    __nv_bfloat16 *Qh, *Ql, *Kh, *Kl, *Vh, *Vl;
    __nv_bfloat16 *Xh, *Xl, *Wqh, *Wql, *Wph, *Wpl, *Yh, *Yl;
    cudaGetSymbolAddress((void**)&qkv, g_qkv);
    cudaGetSymbolAddress((void**)&V, g_v);
    cudaGetSymbolAddress((void**)&Qh, g_qh);
    cudaGetSymbolAddress((void**)&Ql, g_ql);
    cudaGetSymbolAddress((void**)&Kh, g_kh);
    cudaGetSymbolAddress((void**)&Kl, g_kl);
    cudaGetSymbolAddress((void**)&Vh, g_vh);
    cudaGetSymbolAddress((void**)&Vl, g_vl);
    cudaGetSymbolAddress((void**)&Xh, g_xh);
    cudaGetSymbolAddress((void**)&Xl, g_xl);
    cudaGetSymbolAddress((void**)&Wqh, g_wqh);
    cudaGetSymbolAddress((void**)&Wql, g_wql);
    cudaGetSymbolAddress((void**)&Wph, g_wph);
    cudaGetSymbolAddress((void**)&Wpl, g_wpl);
    cudaGetSymbolAddress((void**)&Yh, g_yh);
    cudaGetSymbolAddress((void**)&Yl, g_yl);

    cudaFuncSetAttribute(gemm_bf16s, cudaFuncAttributeMaxDynamicSharedMemorySize, G_SMEM);
    cudaFuncSetAttribute(flash_mma, cudaFuncAttributeMaxDynamicSharedMemorySize, F_SMEM);

    // 0) pre-split operands to bf16 hi/lo
    {
        int n4 = BATCH * SEQ * DMODEL / 4;
        split_kernel<<<(n4 + 255) / 256, 256>>>(x, Xh, Xl, n4);
        n4 = 3 * HDIM * DMODEL / 4;
        split_kernel<<<(n4 + 255) / 256, 256>>>(qkv_w, Wqh, Wql, n4);
        n4 = DMODEL * HDIM / 4;
        split_kernel<<<(n4 + 255) / 256, 256>>>(c_proj_w, Wph, Wpl, n4);
    }

    // 1) qkv = x @ qkv_w^T
    gemm_bf16s<<<dim3(3 * HDIM / 128, BATCH * SEQ / 256), 512, G_SMEM>>>(
        Xh, Xl, Wqh, Wql, qkv, DMODEL, 3 * HDIM);

    // 2) rms-norm + rope + v-mix
    prep_kernel<<<BATCH * SEQ * NH, 128>>>(qkv, ve, lambdas, Qh, Ql, Kh, Kl, V);

    // 2b) V transpose + split
    vtrans_kernel<<<dim3(SEQ / 32, HD / 32, BATCH * NH), 256>>>(V, Vh, Vl);

    // 3) flash attention -> pre-split Yh/Yl
    flash_mma<<<dim3(SEQ / 128, BATCH * NH), 256, F_SMEM>>>(
        Qh, Ql, Kh, Kl, Vh, Vl, Yh, Yl);

    // 4) out = Y @ c_proj_w^T
    gemm_bf16s<<<dim3(DMODEL / 128, BATCH * SEQ / 256), 512, G_SMEM>>>(
        Yh, Yl, Wph, Wpl, out, HDIM, DMODEL);
}

// round 7
// speedup vs baseline: 1.3200x; 1.3200x over previous
#include <cuda_runtime.h>
#include <cuda_fp16.h>
#include <cstdint>
#include <math.h>

#define BATCH 4
#define SEQ   2048
#define DMODEL 1024
#define NH    8
#define HD    128
#define HDIM  1024

// ---------------------------------------------------------------------------
// Scratch (device globals: allocation-free rule)
// ---------------------------------------------------------------------------
__device__ float g_qkv[(size_t)BATCH * SEQ * 3 * HDIM];      // [B,T,3*HDIM]
__device__ float g_v[(size_t)BATCH * NH * SEQ * HD];         // [B,H,T,D] fp32
__device__ __half g_qh[(size_t)BATCH * NH * SEQ * HD];       // [B,H,T,D] split hi
__device__ __half g_ql[(size_t)BATCH * NH * SEQ * HD];       // split lo
__device__ __half g_kh[(size_t)BATCH * NH * SEQ * HD];       // single fp16
__device__ __half g_vh[(size_t)BATCH * NH * HD * SEQ];       // [B,H,D,T] single fp16
// GEMM operands
__device__ __half g_xh[(size_t)BATCH * SEQ * DMODEL];        // x split hi
__device__ __half g_xl[(size_t)BATCH * SEQ * DMODEL];        // x split lo
__device__ __half g_wq[(size_t)3 * HDIM * DMODEL];           // weights single fp16
__device__ __half g_wp[(size_t)DMODEL * HDIM];
__device__ __half g_yh[(size_t)BATCH * SEQ * HDIM];          // flash out split
__device__ __half g_yl[(size_t)BATCH * SEQ * HDIM];

// ---------------------------------------------------------------------------
// PTX helpers
// ---------------------------------------------------------------------------
__device__ __forceinline__ uint32_t smem_u32(const void* p) {
    uint32_t a;
    asm("{ .reg .u64 t; cvta.to.shared.u64 t, %1; cvt.u32.u64 %0, t; }"
        : "=r"(a) : "l"(p));
    return a;
}

#define LDMX4(r, addr) \
    asm volatile("ldmatrix.sync.aligned.m8n8.x4.shared.b16 {%0,%1,%2,%3}, [%4];" \
        : "=r"((r)[0]), "=r"((r)[1]), "=r"((r)[2]), "=r"((r)[3]) : "r"(addr))

#define MMA_F16(d, a, b0, b1) \
    asm volatile("mma.sync.aligned.m16n8k16.row.col.f32.f16.f16.f32 " \
        "{%0,%1,%2,%3},{%4,%5,%6,%7},{%8,%9},{%0,%1,%2,%3};" \
        : "+f"((d)[0]), "+f"((d)[1]), "+f"((d)[2]), "+f"((d)[3]) \
        : "r"((a)[0]), "r"((a)[1]), "r"((a)[2]), "r"((a)[3]), "r"(b0), "r"(b1))

#define CP_ASYNC16(dst, src) \
    asm volatile("cp.async.cg.shared.global [%0], [%1], 16;" :: "r"(dst), "l"(src) : "memory")
#define CP_COMMIT() asm volatile("cp.async.commit_group;" ::: "memory")
#define CP_WAIT0()  asm volatile("cp.async.wait_group 0;" ::: "memory")
#define CP_WAIT1()  asm volatile("cp.async.wait_group 1;" ::: "memory")
#define CP_WAIT2()  asm volatile("cp.async.wait_group 2;" ::: "memory")

// pack two fp32 -> f16x2 (e0 low half, e1 high half)
__device__ __forceinline__ uint32_t packh(float e0, float e1) {
    __half2 h = __floats2half2_rn(e0, e1);
    return *reinterpret_cast<uint32_t*>(&h);
}
__device__ __forceinline__ float hx2_lo(uint32_t p) {
    __half2 h = *reinterpret_cast<__half2*>(&p);
    return __low2float(h);
}
__device__ __forceinline__ float hx2_hi(uint32_t p) {
    __half2 h = *reinterpret_cast<__half2*>(&p);
    return __high2float(h);
}

// ---------------------------------------------------------------------------
// split: fp32 -> fp16 hi/lo (exact to 2^-22)
// ---------------------------------------------------------------------------
__global__ __launch_bounds__(256) void split_kernel(
    const float* __restrict__ src, __half* __restrict__ hi,
    __half* __restrict__ lo, int n4)
{
    int i = blockIdx.x * 256 + threadIdx.x;
    if (i < n4) {
        float4 v = ((const float4*)src)[i];
        uint32_t h0 = packh(v.x, v.y), h1 = packh(v.z, v.w);
        uint32_t l0 = packh(v.x - hx2_lo(h0), v.y - hx2_hi(h0));
        uint32_t l1 = packh(v.z - hx2_lo(h1), v.w - hx2_hi(h1));
        ((uint2*)hi)[i] = make_uint2(h0, h1);
        ((uint2*)lo)[i] = make_uint2(l0, l1);
    }
}

// convert: fp32 -> single fp16
__global__ __launch_bounds__(256) void conv_kernel(
    const float* __restrict__ src, __half* __restrict__ dst, int n4)
{
    int i = blockIdx.x * 256 + threadIdx.x;
    if (i < n4) {
        float4 v = ((const float4*)src)[i];
        ((uint2*)dst)[i] = make_uint2(packh(v.x, v.y), packh(v.z, v.w));
    }
}

// ===========================================================================
// fp16 one-sided-split GEMM: C[M,N](fp32) = (Ah+Al)[M,K] @ B[N,K]^T, 2-term.
// CTA 256x128, 512 threads (16 warps 4x4, warp tile 64x32), K-chunk 32,
// 4-stage cp.async. Stage: Ah|Al (256x80B each) | B (128x80B) = 51200 B.
// ===========================================================================
#define GA_PART  20480
#define GB_PART  10240
#define G_STAGE  (2 * GA_PART + GB_PART)          // 51200
#define G_SMEM   (4 * G_STAGE)                    // 204800

__global__ __launch_bounds__(512, 1) void gemm_f16s(
    const __half* __restrict__ Ah, const __half* __restrict__ Al,
    const __half* __restrict__ Bh,
    float* __restrict__ C, int Kd, int Nd)
{
    extern __shared__ char smem[];
    const uint32_t sb = smem_u32(smem);
    const int tid = threadIdx.x;
    const int wid = tid >> 5, lane = tid & 31;
    const int wm = wid >> 2, wn = wid & 3;
    const int m0 = blockIdx.y * 256, n0 = blockIdx.x * 128;
    const int nch = Kd / 32;

    auto load_stage = [&](int c) {
        const uint32_t st = sb + (c & 3) * G_STAGE;
        const __half* pAh = Ah + (size_t)m0 * Kd + c * 32;
        const __half* pAl = Al + (size_t)m0 * Kd + c * 32;
        const __half* pB  = Bh + (size_t)n0 * Kd + c * 32;
#pragma unroll
        for (int i = 0; i < 2; i++) {
            const int cc = i * 512 + tid;
            const int row = cc >> 2, col = cc & 3;
            const uint32_t off = row * 80 + col * 16;
            const size_t gi = (size_t)row * Kd + col * 8;
            CP_ASYNC16(st + off,           pAh + gi);
            CP_ASYNC16(st + GA_PART + off, pAl + gi);
        }
        {
            const int row = tid >> 2, col = tid & 3;
            const uint32_t off = row * 80 + col * 16;
            const size_t gi = (size_t)row * Kd + col * 8;
            CP_ASYNC16(st + 2 * GA_PART + off, pB + gi);
        }
    };

    float acc[4][4][4];
#pragma unroll
    for (int i = 0; i < 4; i++)
#pragma unroll
        for (int j = 0; j < 4; j++)
#pragma unroll
            for (int e = 0; e < 4; e++) acc[i][j][e] = 0.f;

    auto compute = [&](int s) {
        const uint32_t st = sb + s * G_STAGE;
        const uint32_t lrow = (lane & 15);
        const uint32_t lcol = (lane >> 4) * 16;
#pragma unroll
        for (int k16 = 0; k16 < 2; k16++) {
            const uint32_t kb2 = k16 * 32;
            uint32_t ah[4][4], al[4][4];
#pragma unroll
            for (int i = 0; i < 4; i++) {
                uint32_t aaddr = st + (wm * 64 + i * 16 + lrow) * 80 + kb2 + lcol;
                LDMX4(ah[i], aaddr);
                LDMX4(al[i], aaddr + GA_PART);
            }
            uint32_t b_[4][2];
#pragma unroll
            for (int jj = 0; jj < 2; jj++) {
                uint32_t r[4];
                uint32_t baddr = st + 2 * GA_PART + (wn * 32 + jj * 16 + lrow) * 80 + kb2 + lcol;
                LDMX4(r, baddr);
                b_[2 * jj][0] = r[0]; b_[2 * jj][1] = r[2];
                b_[2 * jj + 1][0] = r[1]; b_[2 * jj + 1][1] = r[3];
            }
#pragma unroll
            for (int i = 0; i < 4; i++)
#pragma unroll
                for (int j = 0; j < 4; j++)
                    MMA_F16(acc[i][j], ah[i], b_[j][0], b_[j][1]);
#pragma unroll
            for (int i = 0; i < 4; i++)
#pragma unroll
                for (int j = 0; j < 4; j++)
                    MMA_F16(acc[i][j], al[i], b_[j][0], b_[j][1]);
        }
    };

    // 4-stage pipeline: prologue 3 loads, steady-state 3 in flight
    load_stage(0); CP_COMMIT();
    load_stage(1); CP_COMMIT();
    load_stage(2); CP_COMMIT();
    for (int c = 0; c < nch; c++) {
        if (c + 2 < nch) CP_WAIT2();
        else if (c + 1 < nch) CP_WAIT1();
        else CP_WAIT0();
        __syncthreads();
        if (c + 3 < nch) { load_stage(c + 3); CP_COMMIT(); }
        compute(c & 3);
    }

    // ---- epilogue ----
    const int r = lane >> 2;
    const int cb = (lane & 3) * 2;
#pragma unroll
    for (int i = 0; i < 4; i++) {
        const int row0 = m0 + wm * 64 + i * 16 + r;
#pragma unroll
        for (int j = 0; j < 4; j++) {
            const int col = n0 + wn * 32 + j * 8 + cb;
            *(float2*)(C + (size_t)row0 * Nd + col) = make_float2(acc[i][j][0], acc[i][j][1]);
            *(float2*)(C + (size_t)(row0 + 8) * Nd + col) = make_float2(acc[i][j][2], acc[i][j][3]);
        }
    }
}

// ---------------------------------------------------------------------------
// prep: per (b,t,h) RMS-norm q,k; RoPE; v-mix. Q split fp16, K single fp16.
// ---------------------------------------------------------------------------
__global__ __launch_bounds__(128) void prep_kernel(
    const float* __restrict__ qkv, const float* __restrict__ ve,
    const float* __restrict__ lam,
    __half* __restrict__ Qh, __half* __restrict__ Ql,
    __half* __restrict__ Kh, float* __restrict__ V)
{
    const int idx = blockIdx.x;
    const int h = idx % NH;
    const int bt = idx / NH;
    const int t = bt % SEQ;
    const int b = bt / SEQ;
    const int d = threadIdx.x;

    const float* base = qkv + (size_t)bt * 3 * HDIM;
    float qv = base[h * HD + d];
    float kv = base[HDIM + h * HD + d];
    float vv = base[2 * HDIM + h * HD + d];

    float sq = qv * qv, sk = kv * kv;
#pragma unroll
    for (int o = 16; o; o >>= 1) {
        sq += __shfl_xor_sync(0xffffffffu, sq, o);
        sk += __shfl_xor_sync(0xffffffffu, sk, o);
    }
    __shared__ float wq[4], wk[4];
    if ((d & 31) == 0) { wq[d >> 5] = sq; wk[d >> 5] = sk; }
    __syncthreads();
    float tq = (wq[0] + wq[1]) + (wq[2] + wq[3]);
    float tk = (wk[0] + wk[1]) + (wk[2] + wk[3]);
    const float EPS = 1.1920929e-7f;
    float rq = rsqrtf(tq * (1.0f / 128.0f) + EPS);
    float rk = rsqrtf(tk * (1.0f / 128.0f) + EPS);

    __shared__ float nq[128], nk[128];
    nq[d] = qv * rq;
    nk[d] = kv * rk;
    __syncthreads();

    const int i = d & 63;
    float c, s;
    if (i < 32) {
        float xi = (float)i / 31.0f;
        float f = (float)exp2(-10.0 * (double)xi);
        float th = (float)t * f;
        c = cosf(th);
        s = sinf(th);
    } else {
        c = 1.0f; s = 0.0f;
    }
    float qo, ko;
    if (d < 64) { qo = nq[d] * c + nq[d + 64] * s; ko = nk[d] * c + nk[d + 64] * s; }
    else        { qo = nq[d] * c - nq[d - 64] * s; ko = nk[d] * c - nk[d - 64] * s; }

    float vo = lam[0] * vv + lam[1] * ve[(size_t)bt * HDIM + h * HD + d];

    size_t o = ((size_t)(b * NH + h) * SEQ + t) * HD + d;
    __half qhi = __float2half_rn(qo);
    Qh[o] = qhi;
    Ql[o] = __float2half_rn(qo - __half2float(qhi));
    Kh[o] = __float2half_rn(ko);
    V[o] = vo;
}

// ---------------------------------------------------------------------------
// vtrans: V [BH][T][D] fp32 -> Vh [BH][D][T] fp16 single
// ---------------------------------------------------------------------------
__global__ __launch_bounds__(256) void vtrans_kernel(
    const float* __restrict__ V, __half* __restrict__ Vh)
{
    __shared__ float tile[32][33];
    const int bh = blockIdx.z;
    const int t0 = blockIdx.x * 32, d0 = blockIdx.y * 32;
    const int tx = threadIdx.x & 31, ty = threadIdx.x >> 5;
    const float* src = V + (size_t)bh * SEQ * HD;
#pragma unroll
    for (int i = 0; i < 4; i++)
        tile[ty + i * 8][tx] = src[(size_t)(t0 + ty + i * 8) * HD + d0 + tx];
    __syncthreads();
    __half* dh = Vh + (size_t)bh * HD * SEQ;
#pragma unroll
    for (int i = 0; i < 4; i++) {
        float v = tile[tx][ty + i * 8];
        dh[(size_t)(d0 + ty + i * 8) * SEQ + t0 + tx] = __float2half_rn(v);
    }
}

// ===========================================================================
// Flash attention, fp16 one-sided-split. 128 q-rows/CTA, 8 warps x 16 rows.
// Q split (2-term S), K single; P split (2-term PV), V single.
// smem: Qh|Ql (34816 each) + 3 stages x (K 17408 | V 18432).
// ===========================================================================
#define FQ_PART 34816
#define FK_PART 17408
#define FV_PART 18432
#define FSTAGE  (FK_PART + FV_PART)               // 35840
#define FSTAGE0 (2 * FQ_PART)                     // 69632
#define F_SMEM  (FSTAGE0 + 3 * FSTAGE)            // 177152

__global__ __launch_bounds__(256, 1) void flash_mma(
    const __half* __restrict__ Qh, const __half* __restrict__ Ql,
    const __half* __restrict__ Kh, const __half* __restrict__ Vh,
    __half* __restrict__ Yh, __half* __restrict__ Yl)
{
    extern __shared__ char smem[];
    const uint32_t sbase = smem_u32(smem);
    const int tid = threadIdx.x;
    const int wid = tid >> 5, lane = tid & 31;
    const int qt = gridDim.x - 1 - blockIdx.x;
    const int bh = blockIdx.y;
    const int b = bh >> 3, h = bh & 7;

    const size_t TD = (size_t)SEQ * HD;
    const __half* qh_b = Qh + bh * TD;
    const __half* ql_b = Ql + bh * TD;
    const __half* kh_b = Kh + bh * TD;
    const __half* vh_b = Vh + bh * TD;

    // Q tile (both parts)
#pragma unroll
    for (int i = 0; i < 16; i++) {
        int c = i * 256 + tid;
        int part = c >> 11;
        int c2 = c & 2047;
        int row = c2 >> 4, col = c2 & 15;
        uint32_t dst = sbase + part * FQ_PART + row * 272 + col * 16;
        const __half* src = (part ? ql_b : qh_b) + (size_t)(qt * 128 + row) * 128 + col * 8;
        CP_ASYNC16(dst, src);
    }
    auto load_kv = [&](int kt, int s) {
        uint32_t kb = sbase + FSTAGE0 + s * FSTAGE;
#pragma unroll
        for (int i = 0; i < 4; i++) {
            int c = i * 256 + tid;
            int row = c >> 4, col = c & 15;
            size_t gi = (size_t)(kt * 64 + row) * 128 + col * 8;
            CP_ASYNC16(kb + row * 272 + col * 16, kh_b + gi);
        }
#pragma unroll
        for (int i = 0; i < 4; i++) {
            int c = i * 256 + tid;
            int row = c >> 3, col = c & 7;
            size_t gi = (size_t)row * SEQ + kt * 64 + col * 8;
            CP_ASYNC16(kb + FK_PART + row * 144 + col * 16, vh_b + gi);
        }
    };
    const int nkt = 2 * qt + 2;
    load_kv(0, 0);
    CP_COMMIT();                      // group: Q + KV0
    load_kv(1, 1);
    CP_COMMIT();

    float acc[16][4];
#pragma unroll
    for (int i = 0; i < 16; i++)
#pragma unroll
        for (int e = 0; e < 4; e++) acc[i][e] = 0.f;
    float m_i[2] = {-1e30f, -1e30f};
    float l_i[2] = {0.f, 0.f};

    const uint32_t lrow = lane & 15;
    const uint32_t lcol = (lane >> 4) * 16;
    const float SC = 0.08838834764831845f;

    for (int kt = 0; kt < nkt; kt++) {
        if (kt + 2 < nkt) {
            load_kv(kt + 2, (kt + 2) % 3);
            CP_COMMIT();
            CP_WAIT2();
        } else if (kt + 1 < nkt) {
            CP_WAIT1();
        } else {
            CP_WAIT0();
        }
        __syncthreads();
        const uint32_t kb = sbase + FSTAGE0 + (kt % 3) * FSTAGE;

        // ---------- S = Q @ K^T (2-term: qh.K + ql.K) ----------
        float s[8][4];
#pragma unroll
        for (int j = 0; j < 8; j++)
#pragma unroll
            for (int e = 0; e < 4; e++) s[j][e] = 0.f;

        const uint32_t qrow = sbase + (wid * 16 + lrow) * 272 + lcol;
#pragma unroll
        for (int k16 = 0; k16 < 8; k16++) {
            uint32_t qa = qrow + k16 * 32;
            uint32_t ah[4], al[4];
            LDMX4(ah, qa);
            LDMX4(al, qa + FQ_PART);
            uint32_t kf[4][4];
#pragma unroll
            for (int jj = 0; jj < 4; jj++) {
                uint32_t ka = kb + (jj * 16 + lrow) * 272 + lcol + k16 * 32;
                LDMX4(kf[jj], ka);
            }
#pragma unroll
            for (int jj = 0; jj < 4; jj++) {
                MMA_F16(s[2 * jj], ah, kf[jj][0], kf[jj][2]);
                MMA_F16(s[2 * jj + 1], ah, kf[jj][1], kf[jj][3]);
            }
#pragma unroll
            for (int jj = 0; jj < 4; jj++) {
                MMA_F16(s[2 * jj], al, kf[jj][0], kf[jj][2]);
                MMA_F16(s[2 * jj + 1], al, kf[jj][1], kf[jj][3]);
            }
        }

        const bool need_mask = (kt >= 2 * qt);
#pragma unroll
        for (int hh = 0; hh < 2; hh++) {
            const int rowg = qt * 128 + wid * 16 + (lane >> 2) + hh * 8;
            float mt = -1e30f;
#pragma unroll
            for (int j = 0; j < 8; j++) {
#pragma unroll
                for (int e = 0; e < 2; e++) {
                    float v = s[j][2 * hh + e] * SC;
                    if (need_mask) {
                        int colg = kt * 64 + j * 8 + (lane & 3) * 2 + e;
                        if (colg > rowg) v = -1e30f;
                    }
                    s[j][2 * hh + e] = v;
                    mt = fmaxf(mt, v);
                }
            }
            mt = fmaxf(mt, __shfl_xor_sync(0xffffffffu, mt, 1));
            mt = fmaxf(mt, __shfl_xor_sync(0xffffffffu, mt, 2));
            float mn = fmaxf(m_i[hh], mt);
            float corr = __expf(m_i[hh] - mn);
            m_i[hh] = mn;
            float rs = 0.f;
#pragma unroll
            for (int j = 0; j < 8; j++) {
#pragma unroll
                for (int e = 0; e < 2; e++) {
                    float p = __expf(s[j][2 * hh + e] - mn);
                    s[j][2 * hh + e] = p;
                    rs += p;
                }
            }
            rs += __shfl_xor_sync(0xffffffffu, rs, 1);
            rs += __shfl_xor_sync(0xffffffffu, rs, 2);
            l_i[hh] = l_i[hh] * corr + rs;
#pragma unroll
            for (int ot = 0; ot < 16; ot++) {
                acc[ot][2 * hh] *= corr;
                acc[ot][2 * hh + 1] *= corr;
            }
        }

        // ---------- acc += P @ V (2-term: ph.V + pl.V) ----------
        const uint32_t vb = kb + FK_PART;
#pragma unroll
        for (int kk = 0; kk < 4; kk++) {
            const int j0 = 2 * kk, j1 = 2 * kk + 1;
            uint32_t ahp[4], alp[4];
            ahp[0] = packh(s[j0][0], s[j0][1]);
            ahp[1] = packh(s[j0][2], s[j0][3]);
            ahp[2] = packh(s[j1][0], s[j1][1]);
            ahp[3] = packh(s[j1][2], s[j1][3]);
            alp[0] = packh(s[j0][0] - hx2_lo(ahp[0]), s[j0][1] - hx2_hi(ahp[0]));
            alp[1] = packh(s[j0][2] - hx2_lo(ahp[1]), s[j0][3] - hx2_hi(ahp[1]));
            alp[2] = packh(s[j1][0] - hx2_lo(ahp[2]), s[j1][1] - hx2_hi(ahp[2]));
            alp[3] = packh(s[j1][2] - hx2_lo(ahp[3]), s[j1][3] - hx2_hi(ahp[3]));
#pragma unroll
            for (int jp = 0; jp < 4; jp++) {
                const int ja = 2 * jp, jb = 2 * jp + 1;
                uint32_t rA[4], rB[4];
                LDMX4(rA, vb + (ja * 16 + lrow) * 144 + kk * 32 + lcol);
                LDMX4(rB, vb + (jb * 16 + lrow) * 144 + kk * 32 + lcol);
                MMA_F16(acc[2 * ja], ahp, rA[0], rA[2]);
                MMA_F16(acc[2 * ja + 1], ahp, rA[1], rA[3]);
                MMA_F16(acc[2 * jb], ahp, rB[0], rB[2]);
                MMA_F16(acc[2 * jb + 1], ahp, rB[1], rB[3]);
                MMA_F16(acc[2 * ja], alp, rA[0], rA[2]);
                MMA_F16(acc[2 * ja + 1], alp, rA[1], rA[3]);
                MMA_F16(acc[2 * jb], alp, rB[0], rB[2]);
                MMA_F16(acc[2 * jb + 1], alp, rB[1], rB[3]);
            }
        }
        __syncthreads();
    }

    // ---------- epilogue: write pre-split fp16 Y ----------
    const float inv0 = 1.f / l_i[0];
    const float inv1 = 1.f / l_i[1];
    const int r0 = qt * 128 + wid * 16 + (lane >> 2);
    const int cb = (lane & 3) * 2;
#pragma unroll
    for (int ot = 0; ot < 16; ot++) {
        const int d = ot * 8 + cb;
        size_t o0 = ((size_t)b * SEQ + r0) * HDIM + h * HD + d;
        size_t o1 = o0 + (size_t)8 * HDIM;
        float a0 = acc[ot][0] * inv0, a1 = acc[ot][1] * inv0;
        float a2 = acc[ot][2] * inv1, a3 = acc[ot][3] * inv1;
        uint32_t h0 = packh(a0, a1);
        uint32_t l0 = packh(a0 - hx2_lo(h0), a1 - hx2_hi(h0));
        uint32_t h1 = packh(a2, a3);
        uint32_t l1 = packh(a2 - hx2_lo(h1), a3 - hx2_hi(h1));
        *(uint32_t*)(Yh + o0) = h0;
        *(uint32_t*)(Yl + o0) = l0;
        *(uint32_t*)(Yh + o1) = h1;
        *(uint32_t*)(Yl + o1) = l1;
    }
}

// ---------------------------------------------------------------------------
extern "C" void kernel_launch(void* const* d_in, const int* in_sizes, int n_in,
                              void* d_out, int out_size)
{
    const float* x        = (const float*)d_in[0];
    const float* ve       = (const float*)d_in[1];
    const float* qkv_w    = (const float*)d_in[2];   // [3*HDIM, DIM]
    const float* lambdas  = (const float*)d_in[3];
    const float* c_proj_w = (const float*)d_in[4];   // [DIM, HDIM]
    float* out = (float*)d_out;

    float *qkv, *V;
    __half *Qh, *Ql, *Kh, *Vh, *Xh, *Xl, *Wq, *Wp, *Yh, *Yl;
    cudaGetSymbolAddress((void**)&qkv, g_qkv);
    cudaGetSymbolAddress((void**)&V, g_v);
    cudaGetSymbolAddress((void**)&Qh, g_qh);
    cudaGetSymbolAddress((void**)&Ql, g_ql);
    cudaGetSymbolAddress((void**)&Kh, g_kh);
    cudaGetSymbolAddress((void**)&Vh, g_vh);
    cudaGetSymbolAddress((void**)&Xh, g_xh);
    cudaGetSymbolAddress((void**)&Xl, g_xl);
    cudaGetSymbolAddress((void**)&Wq, g_wq);
    cudaGetSymbolAddress((void**)&Wp, g_wp);
    cudaGetSymbolAddress((void**)&Yh, g_yh);
    cudaGetSymbolAddress((void**)&Yl, g_yl);

    cudaFuncSetAttribute(gemm_f16s, cudaFuncAttributeMaxDynamicSharedMemorySize, G_SMEM);
    cudaFuncSetAttribute(flash_mma, cudaFuncAttributeMaxDynamicSharedMemorySize, F_SMEM);

    // 0) operand conversion
    {
        int n4 = BATCH * SEQ * DMODEL / 4;
        split_kernel<<<(n4 + 255) / 256, 256>>>(x, Xh, Xl, n4);
        n4 = 3 * HDIM * DMODEL / 4;
        conv_kernel<<<(n4 + 255) / 256, 256>>>(qkv_w, Wq, n4);
        n4 = DMODEL * HDIM / 4;
        conv_kernel<<<(n4 + 255) / 256, 256>>>(c_proj_w, Wp, n4);
    }

    // 1) qkv = x @ qkv_w^T
    gemm_f16s<<<dim3(3 * HDIM / 128, BATCH * SEQ / 256), 512, G_SMEM>>>(
        Xh, Xl, Wq, qkv, DMODEL, 3 * HDIM);

    // 2) rms-norm + rope + v-mix
    prep_kernel<<<BATCH * SEQ * NH, 128>>>(qkv, ve, lambdas, Qh, Ql, Kh, V);

    // 2b) V transpose -> fp16 [B,H,D,T]
    vtrans_kernel<<<dim3(SEQ / 32, HD / 32, BATCH * NH), 256>>>(V, Vh);

    // 3) flash attention -> pre-split Yh/Yl
    flash_mma<<<dim3(SEQ / 128, BATCH * NH), 256, F_SMEM>>>(
        Qh, Ql, Kh, Vh, Yh, Yl);

    // 4) out = Y @ c_proj_w^T
    gemm_f16s<<<dim3(DMODEL / 128, BATCH * SEQ / 256), 512, G_SMEM>>>(
        Yh, Yl, Wp, out, HDIM, DMODEL);
}

// round 8
// speedup vs baseline: 1.4505x; 1.0989x over previous
#include <cuda_runtime.h>
#include <cuda_fp16.h>
#include <cstdint>
#include <math.h>

#define BATCH 4
#define SEQ   2048
#define DMODEL 1024
#define NH    8
#define HD    128
#define HDIM  1024

// ---------------------------------------------------------------------------
// Scratch (device globals: allocation-free rule)
// ---------------------------------------------------------------------------
__device__ __half g_qh[(size_t)BATCH * NH * SEQ * HD];       // [B,H,T,D] split hi
__device__ __half g_ql[(size_t)BATCH * NH * SEQ * HD];       // split lo
__device__ __half g_kh[(size_t)BATCH * NH * SEQ * HD];       // single fp16
__device__ __half g_vh[(size_t)BATCH * NH * HD * SEQ];       // [B,H,D,T] single fp16
__device__ __half g_xh[(size_t)BATCH * SEQ * DMODEL];        // x split hi
__device__ __half g_xl[(size_t)BATCH * SEQ * DMODEL];        // x split lo
__device__ __half g_wq[(size_t)3 * HDIM * DMODEL];           // weights single fp16
__device__ __half g_wp[(size_t)DMODEL * HDIM];
__device__ __half g_yh[(size_t)BATCH * SEQ * HDIM];          // flash out split
__device__ __half g_yl[(size_t)BATCH * SEQ * HDIM];

// ---------------------------------------------------------------------------
// PTX helpers
// ---------------------------------------------------------------------------
__device__ __forceinline__ uint32_t smem_u32(const void* p) {
    uint32_t a;
    asm("{ .reg .u64 t; cvta.to.shared.u64 t, %1; cvt.u32.u64 %0, t; }"
        : "=r"(a) : "l"(p));
    return a;
}

#define LDMX4(r, addr) \
    asm volatile("ldmatrix.sync.aligned.m8n8.x4.shared.b16 {%0,%1,%2,%3}, [%4];" \
        : "=r"((r)[0]), "=r"((r)[1]), "=r"((r)[2]), "=r"((r)[3]) : "r"(addr))

#define MMA_F16(d, a, b0, b1) \
    asm volatile("mma.sync.aligned.m16n8k16.row.col.f32.f16.f16.f32 " \
        "{%0,%1,%2,%3},{%4,%5,%6,%7},{%8,%9},{%0,%1,%2,%3};" \
        : "+f"((d)[0]), "+f"((d)[1]), "+f"((d)[2]), "+f"((d)[3]) \
        : "r"((a)[0]), "r"((a)[1]), "r"((a)[2]), "r"((a)[3]), "r"(b0), "r"(b1))

#define CP_ASYNC16(dst, src) \
    asm volatile("cp.async.cg.shared.global [%0], [%1], 16;" :: "r"(dst), "l"(src) : "memory")
#define CP_COMMIT() asm volatile("cp.async.commit_group;" ::: "memory")
#define CP_WAIT0()  asm volatile("cp.async.wait_group 0;" ::: "memory")
#define CP_WAIT1()  asm volatile("cp.async.wait_group 1;" ::: "memory")
#define CP_WAIT2()  asm volatile("cp.async.wait_group 2;" ::: "memory")

__device__ __forceinline__ uint32_t packh(float e0, float e1) {
    __half2 h = __floats2half2_rn(e0, e1);
    return *reinterpret_cast<uint32_t*>(&h);
}
__device__ __forceinline__ float hx2_lo(uint32_t p) {
    __half2 h = *reinterpret_cast<__half2*>(&p);
    return __low2float(h);
}
__device__ __forceinline__ float hx2_hi(uint32_t p) {
    __half2 h = *reinterpret_cast<__half2*>(&p);
    return __high2float(h);
}

// ---------------------------------------------------------------------------
// split: fp32 -> fp16 hi/lo (exact to 2^-22); conv: fp32 -> fp16
// ---------------------------------------------------------------------------
__global__ __launch_bounds__(256) void split_kernel(
    const float* __restrict__ src, __half* __restrict__ hi,
    __half* __restrict__ lo, int n4)
{
    int i = blockIdx.x * 256 + threadIdx.x;
    if (i < n4) {
        float4 v = ((const float4*)src)[i];
        uint32_t h0 = packh(v.x, v.y), h1 = packh(v.z, v.w);
        uint32_t l0 = packh(v.x - hx2_lo(h0), v.y - hx2_hi(h0));
        uint32_t l1 = packh(v.z - hx2_lo(h1), v.w - hx2_hi(h1));
        ((uint2*)hi)[i] = make_uint2(h0, h1);
        ((uint2*)lo)[i] = make_uint2(l0, l1);
    }
}

__global__ __launch_bounds__(256) void conv_kernel(
    const float* __restrict__ src, __half* __restrict__ dst, int n4)
{
    int i = blockIdx.x * 256 + threadIdx.x;
    if (i < n4) {
        float4 v = ((const float4*)src)[i];
        ((uint2*)dst)[i] = make_uint2(packh(v.x, v.y), packh(v.z, v.w));
    }
}

// ===========================================================================
// fp16 one-sided-split GEMM, CTA 256x128, 512 thr, 4-stage cp.async.
// fused=0: plain fp32 C write (c_proj).
// fused=1: qkv epilogue — RMS-norm + RoPE + v-mix + layout + splits, writing
//          Qh/Ql/Kh [B,H,T,D] and Vh [B,H,D,T] directly (no fp32 qkv array).
// Epilogue smem reuse: tile fp32 [256][132] | rowscale [256] | trig [256][32][2]
// = 135168 + 1024 + 65536 = 201728 <= G_SMEM.
// ===========================================================================
#define GA_PART  20480
#define GB_PART  10240
#define G_STAGE  (2 * GA_PART + GB_PART)          // 51200
#define G_SMEM   (4 * G_STAGE)                    // 204800

__global__ __launch_bounds__(512, 1) void gemm_f16s(
    const __half* __restrict__ Ah, const __half* __restrict__ Al,
    const __half* __restrict__ Bh,
    float* __restrict__ C, int Kd, int Nd, int fused,
    __half* __restrict__ Qh, __half* __restrict__ Ql,
    __half* __restrict__ Kh, __half* __restrict__ Vh,
    const float* __restrict__ ve, const float* __restrict__ lam)
{
    extern __shared__ char smem[];
    const uint32_t sb = smem_u32(smem);
    const int tid = threadIdx.x;
    const int wid = tid >> 5, lane = tid & 31;
    const int wm = wid >> 2, wn = wid & 3;
    const int m0 = blockIdx.y * 256, n0 = blockIdx.x * 128;
    const int nch = Kd / 32;

    auto load_stage = [&](int c) {
        const uint32_t st = sb + (c & 3) * G_STAGE;
        const __half* pAh = Ah + (size_t)m0 * Kd + c * 32;
        const __half* pAl = Al + (size_t)m0 * Kd + c * 32;
        const __half* pB  = Bh + (size_t)n0 * Kd + c * 32;
#pragma unroll
        for (int i = 0; i < 2; i++) {
            const int cc = i * 512 + tid;
            const int row = cc >> 2, col = cc & 3;
            const uint32_t off = row * 80 + col * 16;
            const size_t gi = (size_t)row * Kd + col * 8;
            CP_ASYNC16(st + off,           pAh + gi);
            CP_ASYNC16(st + GA_PART + off, pAl + gi);
        }
        {
            const int row = tid >> 2, col = tid & 3;
            const uint32_t off = row * 80 + col * 16;
            const size_t gi = (size_t)row * Kd + col * 8;
            CP_ASYNC16(st + 2 * GA_PART + off, pB + gi);
        }
    };

    float acc[4][4][4];
#pragma unroll
    for (int i = 0; i < 4; i++)
#pragma unroll
        for (int j = 0; j < 4; j++)
#pragma unroll
            for (int e = 0; e < 4; e++) acc[i][j][e] = 0.f;

    auto compute = [&](int s) {
        const uint32_t st = sb + s * G_STAGE;
        const uint32_t lrow = (lane & 15);
        const uint32_t lcol = (lane >> 4) * 16;
#pragma unroll
        for (int k16 = 0; k16 < 2; k16++) {
            const uint32_t kb2 = k16 * 32;
            uint32_t ah[4][4], al[4][4];
#pragma unroll
            for (int i = 0; i < 4; i++) {
                uint32_t aaddr = st + (wm * 64 + i * 16 + lrow) * 80 + kb2 + lcol;
                LDMX4(ah[i], aaddr);
                LDMX4(al[i], aaddr + GA_PART);
            }
            uint32_t b_[4][2];
#pragma unroll
            for (int jj = 0; jj < 2; jj++) {
                uint32_t r[4];
                uint32_t baddr = st + 2 * GA_PART + (wn * 32 + jj * 16 + lrow) * 80 + kb2 + lcol;
                LDMX4(r, baddr);
                b_[2 * jj][0] = r[0]; b_[2 * jj][1] = r[2];
                b_[2 * jj + 1][0] = r[1]; b_[2 * jj + 1][1] = r[3];
            }
#pragma unroll
            for (int i = 0; i < 4; i++)
#pragma unroll
                for (int j = 0; j < 4; j++)
                    MMA_F16(acc[i][j], ah[i], b_[j][0], b_[j][1]);
#pragma unroll
            for (int i = 0; i < 4; i++)
#pragma unroll
                for (int j = 0; j < 4; j++)
                    MMA_F16(acc[i][j], al[i], b_[j][0], b_[j][1]);
        }
    };

    load_stage(0); CP_COMMIT();
    load_stage(1); CP_COMMIT();
    load_stage(2); CP_COMMIT();
    for (int c = 0; c < nch; c++) {
        if (c + 2 < nch) CP_WAIT2();
        else if (c + 1 < nch) CP_WAIT1();
        else CP_WAIT0();
        __syncthreads();
        if (c + 3 < nch) { load_stage(c + 3); CP_COMMIT(); }
        compute(c & 3);
    }

    const int r = lane >> 2;
    const int cb = (lane & 3) * 2;

    if (!fused) {
        // ---- plain epilogue (c_proj) ----
#pragma unroll
        for (int i = 0; i < 4; i++) {
            const int row0 = m0 + wm * 64 + i * 16 + r;
#pragma unroll
            for (int j = 0; j < 4; j++) {
                const int col = n0 + wn * 32 + j * 8 + cb;
                *(float2*)(C + (size_t)row0 * Nd + col) = make_float2(acc[i][j][0], acc[i][j][1]);
                *(float2*)(C + (size_t)(row0 + 8) * Nd + col) = make_float2(acc[i][j][2], acc[i][j][3]);
            }
        }
        return;
    }

    // ======================= fused qkv epilogue ==========================
    float* tile = (float*)smem;              // [256][132]
    float* rsc  = tile + 256 * 132;          // [256]
    float* trig = rsc + 256;                 // [256][32][2] cos,sin

    __syncthreads();   // mainloop smem dead; repurpose

    // 1) stage fp32 tile
#pragma unroll
    for (int i = 0; i < 4; i++) {
        const int row = wm * 64 + i * 16 + r;
#pragma unroll
        for (int j = 0; j < 4; j++) {
            const int col = wn * 32 + j * 8 + cb;
            *(float2*)(tile + row * 132 + col) = make_float2(acc[i][j][0], acc[i][j][1]);
            *(float2*)(tile + (row + 8) * 132 + col) = make_float2(acc[i][j][2], acc[i][j][3]);
        }
    }

    const int part = n0 >> 7;        // 0..23
    const int kind = part >> 3;      // 0=q 1=k 2=v
    const int h = part & 7;

    if (kind < 2) {
        __syncthreads();
        // 2) per-row RMS scale (2 threads per row, 64 cols each)
        {
            const int row = tid >> 1, hs = tid & 1;
            const float* tr = tile + row * 132 + hs * 64;
            float s = 0.f;
#pragma unroll
            for (int k4 = 0; k4 < 16; k4++) {
                float4 v = *(const float4*)(tr + k4 * 4);
                s += v.x * v.x + v.y * v.y + v.z * v.z + v.w * v.w;
            }
            s += __shfl_xor_sync(0xffffffffu, s, 1);
            if (hs == 0)
                rsc[row] = rsqrtf(s * (1.0f / 128.0f) + 1.1920929e-7f);
        }
        // 3) sincos table: 256 rows x 32 freqs
        for (int e = tid; e < 8192; e += 512) {
            const int row = e >> 5, i = e & 31;
            const float xi = (float)i / 31.0f;
            const float f = (float)exp2(-10.0 * (double)xi);
            const int t = (m0 + row) & (SEQ - 1);
            const float th = (float)t * f;
            trig[e * 2]     = cosf(th);
            trig[e * 2 + 1] = sinf(th);
        }
        __syncthreads();

        // 4) RoPE + write (Q split / K single), [B,H,T,D]
        const int dd = (tid & 63) * 2;
        const int rg = tid >> 6;
#pragma unroll 4
        for (int stp = 0; stp < 32; stp++) {
            const int row = rg + stp * 8;
            const float sc = rsc[row];
            float out[2];
#pragma unroll
            for (int e = 0; e < 2; e++) {
                const int d = dd + e;
                const float n = tile[row * 132 + d] * sc;
                const int il = d & 63;
                float cth, sth;
                if (il < 32) {
                    cth = trig[(row * 32 + il) * 2];
                    sth = trig[(row * 32 + il) * 2 + 1];
                } else { cth = 1.f; sth = 0.f; }
                const float partner = tile[row * 132 + (d < 64 ? d + 64 : d - 64)] * sc;
                out[e] = (d < 64) ? (n * cth + partner * sth)
                                  : (n * cth - partner * sth);
            }
            const int m = m0 + row;
            const int b = m >> 11, t = m & (SEQ - 1);
            const size_t o = (((size_t)(b * NH + h)) * SEQ + t) * HD + dd;
            if (kind == 0) {
                uint32_t hh = packh(out[0], out[1]);
                uint32_t ll = packh(out[0] - hx2_lo(hh), out[1] - hx2_hi(hh));
                *(uint32_t*)(Qh + o) = hh;
                *(uint32_t*)(Ql + o) = ll;
            } else {
                *(uint32_t*)(Kh + o) = packh(out[0], out[1]);
            }
        }
    } else {
        // 5) V: lambda-mix with ve (coalesced), then transposed write [B,H,D,T]
        const float l0 = lam[0], l1 = lam[1];
        __syncthreads();
        for (int e = tid; e < 32768; e += 512) {
            const int row = e >> 7, d = e & 127;
            const int m = m0 + row;
            const float vv = ve[(size_t)m * HDIM + h * HD + d];
            tile[row * 132 + d] = l0 * tile[row * 132 + d] + l1 * vv;
        }
        __syncthreads();
        const int d = tid >> 2;
        const int tq = (tid & 3) * 64;
        const int b = m0 >> 11, tbase = m0 & (SEQ - 1);
        const size_t obase = (((size_t)(b * NH + h)) * HD + d) * SEQ + tbase + tq;
#pragma unroll 8
        for (int k = 0; k < 64; k += 2) {
            const float v0 = tile[(tq + k) * 132 + d];
            const float v1 = tile[(tq + k + 1) * 132 + d];
            *(uint32_t*)(Vh + obase + k) = packh(v0, v1);
        }
    }
}

// ===========================================================================
// Flash attention, fp16 one-sided-split. 128 q-rows/CTA, 8 warps x 16 rows.
// ===========================================================================
#define FQ_PART 34816
#define FK_PART 17408
#define FV_PART 18432
#define FSTAGE  (FK_PART + FV_PART)
#define FSTAGE0 (2 * FQ_PART)
#define F_SMEM  (FSTAGE0 + 3 * FSTAGE)

__global__ __launch_bounds__(256, 1) void flash_mma(
    const __half* __restrict__ Qh, const __half* __restrict__ Ql,
    const __half* __restrict__ Kh, const __half* __restrict__ Vh,
    __half* __restrict__ Yh, __half* __restrict__ Yl)
{
    extern __shared__ char smem[];
    const uint32_t sbase = smem_u32(smem);
    const int tid = threadIdx.x;
    const int wid = tid >> 5, lane = tid & 31;
    const int qt = gridDim.x - 1 - blockIdx.x;
    const int bh = blockIdx.y;
    const int b = bh >> 3, h = bh & 7;

    const size_t TD = (size_t)SEQ * HD;
    const __half* qh_b = Qh + bh * TD;
    const __half* ql_b = Ql + bh * TD;
    const __half* kh_b = Kh + bh * TD;
    const __half* vh_b = Vh + bh * TD;

#pragma unroll
    for (int i = 0; i < 16; i++) {
        int c = i * 256 + tid;
        int part = c >> 11;
        int c2 = c & 2047;
        int row = c2 >> 4, col = c2 & 15;
        uint32_t dst = sbase + part * FQ_PART + row * 272 + col * 16;
        const __half* src = (part ? ql_b : qh_b) + (size_t)(qt * 128 + row) * 128 + col * 8;
        CP_ASYNC16(dst, src);
    }
    auto load_kv = [&](int kt, int s) {
        uint32_t kb = sbase + FSTAGE0 + s * FSTAGE;
#pragma unroll
        for (int i = 0; i < 4; i++) {
            int c = i * 256 + tid;
            int row = c >> 4, col = c & 15;
            size_t gi = (size_t)(kt * 64 + row) * 128 + col * 8;
            CP_ASYNC16(kb + row * 272 + col * 16, kh_b + gi);
        }
#pragma unroll
        for (int i = 0; i < 4; i++) {
            int c = i * 256 + tid;
            int row = c >> 3, col = c & 7;
            size_t gi = (size_t)row * SEQ + kt * 64 + col * 8;
            CP_ASYNC16(kb + FK_PART + row * 144 + col * 16, vh_b + gi);
        }
    };
    const int nkt = 2 * qt + 2;
    load_kv(0, 0);
    CP_COMMIT();
    load_kv(1, 1);
    CP_COMMIT();

    float acc[16][4];
#pragma unroll
    for (int i = 0; i < 16; i++)
#pragma unroll
        for (int e = 0; e < 4; e++) acc[i][e] = 0.f;
    float m_i[2] = {-1e30f, -1e30f};
    float l_i[2] = {0.f, 0.f};

    const uint32_t lrow = lane & 15;
    const uint32_t lcol = (lane >> 4) * 16;
    const float SC = 0.08838834764831845f;

    for (int kt = 0; kt < nkt; kt++) {
        if (kt + 2 < nkt) {
            load_kv(kt + 2, (kt + 2) % 3);
            CP_COMMIT();
            CP_WAIT2();
        } else if (kt + 1 < nkt) {
            CP_WAIT1();
        } else {
            CP_WAIT0();
        }
        __syncthreads();
        const uint32_t kb = sbase + FSTAGE0 + (kt % 3) * FSTAGE;

        float s[8][4];
#pragma unroll
        for (int j = 0; j < 8; j++)
#pragma unroll
            for (int e = 0; e < 4; e++) s[j][e] = 0.f;

        const uint32_t qrow = sbase + (wid * 16 + lrow) * 272 + lcol;
#pragma unroll
        for (int k16 = 0; k16 < 8; k16++) {
            uint32_t qa = qrow + k16 * 32;
            uint32_t ah[4], al[4];
            LDMX4(ah, qa);
            LDMX4(al, qa + FQ_PART);
            uint32_t kf[4][4];
#pragma unroll
            for (int jj = 0; jj < 4; jj++) {
                uint32_t ka = kb + (jj * 16 + lrow) * 272 + lcol + k16 * 32;
                LDMX4(kf[jj], ka);
            }
#pragma unroll
            for (int jj = 0; jj < 4; jj++) {
                MMA_F16(s[2 * jj], ah, kf[jj][0], kf[jj][2]);
                MMA_F16(s[2 * jj + 1], ah, kf[jj][1], kf[jj][3]);
            }
#pragma unroll
            for (int jj = 0; jj < 4; jj++) {
                MMA_F16(s[2 * jj], al, kf[jj][0], kf[jj][2]);
                MMA_F16(s[2 * jj + 1], al, kf[jj][1], kf[jj][3]);
            }
        }

        const bool need_mask = (kt >= 2 * qt);
#pragma unroll
        for (int hh = 0; hh < 2; hh++) {
            const int rowg = qt * 128 + wid * 16 + (lane >> 2) + hh * 8;
            float mt = -1e30f;
#pragma unroll
            for (int j = 0; j < 8; j++) {
#pragma unroll
                for (int e = 0; e < 2; e++) {
                    float v = s[j][2 * hh + e] * SC;
                    if (need_mask) {
                        int colg = kt * 64 + j * 8 + (lane & 3) * 2 + e;
                        if (colg > rowg) v = -1e30f;
                    }
                    s[j][2 * hh + e] = v;
                    mt = fmaxf(mt, v);
                }
            }
            mt = fmaxf(mt, __shfl_xor_sync(0xffffffffu, mt, 1));
            mt = fmaxf(mt, __shfl_xor_sync(0xffffffffu, mt, 2));
            float mn = fmaxf(m_i[hh], mt);
            float corr = __expf(m_i[hh] - mn);
            m_i[hh] = mn;
            float rs = 0.f;
#pragma unroll
            for (int j = 0; j < 8; j++) {
#pragma unroll
                for (int e = 0; e < 2; e++) {
                    float p = __expf(s[j][2 * hh + e] - mn);
                    s[j][2 * hh + e] = p;
                    rs += p;
                }
            }
            rs += __shfl_xor_sync(0xffffffffu, rs, 1);
            rs += __shfl_xor_sync(0xffffffffu, rs, 2);
            l_i[hh] = l_i[hh] * corr + rs;
#pragma unroll
            for (int ot = 0; ot < 16; ot++) {
                acc[ot][2 * hh] *= corr;
                acc[ot][2 * hh + 1] *= corr;
            }
        }

        const uint32_t vb = kb + FK_PART;
#pragma unroll
        for (int kk = 0; kk < 4; kk++) {
            const int j0 = 2 * kk, j1 = 2 * kk + 1;
            uint32_t ahp[4], alp[4];
            ahp[0] = packh(s[j0][0], s[j0][1]);
            ahp[1] = packh(s[j0][2], s[j0][3]);
            ahp[2] = packh(s[j1][0], s[j1][1]);
            ahp[3] = packh(s[j1][2], s[j1][3]);
            alp[0] = packh(s[j0][0] - hx2_lo(ahp[0]), s[j0][1] - hx2_hi(ahp[0]));
            alp[1] = packh(s[j0][2] - hx2_lo(ahp[1]), s[j0][3] - hx2_hi(ahp[1]));
            alp[2] = packh(s[j1][0] - hx2_lo(ahp[2]), s[j1][1] - hx2_hi(ahp[2]));
            alp[3] = packh(s[j1][2] - hx2_lo(ahp[3]), s[j1][3] - hx2_hi(ahp[3]));
#pragma unroll
            for (int jp = 0; jp < 4; jp++) {
                const int ja = 2 * jp, jb = 2 * jp + 1;
                uint32_t rA[4], rB[4];
                LDMX4(rA, vb + (ja * 16 + lrow) * 144 + kk * 32 + lcol);
                LDMX4(rB, vb + (jb * 16 + lrow) * 144 + kk * 32 + lcol);
                MMA_F16(acc[2 * ja], ahp, rA[0], rA[2]);
                MMA_F16(acc[2 * ja + 1], ahp, rA[1], rA[3]);
                MMA_F16(acc[2 * jb], ahp, rB[0], rB[2]);
                MMA_F16(acc[2 * jb + 1], ahp, rB[1], rB[3]);
                MMA_F16(acc[2 * ja], alp, rA[0], rA[2]);
                MMA_F16(acc[2 * ja + 1], alp, rA[1], rA[3]);
                MMA_F16(acc[2 * jb], alp, rB[0], rB[2]);
                MMA_F16(acc[2 * jb + 1], alp, rB[1], rB[3]);
            }
        }
        __syncthreads();
    }

    const float inv0 = 1.f / l_i[0];
    const float inv1 = 1.f / l_i[1];
    const int r0 = qt * 128 + wid * 16 + (lane >> 2);
    const int cb = (lane & 3) * 2;
#pragma unroll
    for (int ot = 0; ot < 16; ot++) {
        const int d = ot * 8 + cb;
        size_t o0 = ((size_t)b * SEQ + r0) * HDIM + h * HD + d;
        size_t o1 = o0 + (size_t)8 * HDIM;
        float a0 = acc[ot][0] * inv0, a1 = acc[ot][1] * inv0;
        float a2 = acc[ot][2] * inv1, a3 = acc[ot][3] * inv1;
        uint32_t h0 = packh(a0, a1);
        uint32_t l0 = packh(a0 - hx2_lo(h0), a1 - hx2_hi(h0));
        uint32_t h1 = packh(a2, a3);
        uint32_t l1 = packh(a2 - hx2_lo(h1), a3 - hx2_hi(h1));
        *(uint32_t*)(Yh + o0) = h0;
        *(uint32_t*)(Yl + o0) = l0;
        *(uint32_t*)(Yh + o1) = h1;
        *(uint32_t*)(Yl + o1) = l1;
    }
}

// ---------------------------------------------------------------------------
extern "C" void kernel_launch(void* const* d_in, const int* in_sizes, int n_in,
                              void* d_out, int out_size)
{
    const float* x        = (const float*)d_in[0];
    const float* ve       = (const float*)d_in[1];
    const float* qkv_w    = (const float*)d_in[2];   // [3*HDIM, DIM]
    const float* lambdas  = (const float*)d_in[3];
    const float* c_proj_w = (const float*)d_in[4];   // [DIM, HDIM]
    float* out = (float*)d_out;

    __half *Qh, *Ql, *Kh, *Vh, *Xh, *Xl, *Wq, *Wp, *Yh, *Yl;
    cudaGetSymbolAddress((void**)&Qh, g_qh);
    cudaGetSymbolAddress((void**)&Ql, g_ql);
    cudaGetSymbolAddress((void**)&Kh, g_kh);
    cudaGetSymbolAddress((void**)&Vh, g_vh);
    cudaGetSymbolAddress((void**)&Xh, g_xh);
    cudaGetSymbolAddress((void**)&Xl, g_xl);
    cudaGetSymbolAddress((void**)&Wq, g_wq);
    cudaGetSymbolAddress((void**)&Wp, g_wp);
    cudaGetSymbolAddress((void**)&Yh, g_yh);
    cudaGetSymbolAddress((void**)&Yl, g_yl);

    cudaFuncSetAttribute(gemm_f16s, cudaFuncAttributeMaxDynamicSharedMemorySize, G_SMEM);
    cudaFuncSetAttribute(flash_mma, cudaFuncAttributeMaxDynamicSharedMemorySize, F_SMEM);

    // 0) operand conversion
    {
        int n4 = BATCH * SEQ * DMODEL / 4;
        split_kernel<<<(n4 + 255) / 256, 256>>>(x, Xh, Xl, n4);
        n4 = 3 * HDIM * DMODEL / 4;
        conv_kernel<<<(n4 + 255) / 256, 256>>>(qkv_w, Wq, n4);
        n4 = DMODEL * HDIM / 4;
        conv_kernel<<<(n4 + 255) / 256, 256>>>(c_proj_w, Wp, n4);
    }

    // 1) fused qkv GEMM + rms/rope/v-mix/layout -> Qh,Ql,Kh,Vh
    gemm_f16s<<<dim3(3 * HDIM / 128, BATCH * SEQ / 256), 512, G_SMEM>>>(
        Xh, Xl, Wq, nullptr, DMODEL, 3 * HDIM, 1,
        Qh, Ql, Kh, Vh, ve, lambdas);

    // 2) flash attention -> pre-split Yh/Yl
    flash_mma<<<dim3(SEQ / 128, BATCH * NH), 256, F_SMEM>>>(
        Qh, Ql, Kh, Vh, Yh, Yl);

    // 3) out = Y @ c_proj_w^T
    gemm_f16s<<<dim3(DMODEL / 128, BATCH * SEQ / 256), 512, G_SMEM>>>(
        Yh, Yl, Wp, out, HDIM, DMODEL, 0,
        nullptr, nullptr, nullptr, nullptr, nullptr, nullptr);
}

// round 9
// speedup vs baseline: 2.3339x; 1.6090x over previous
#include <cuda_runtime.h>
#include <cuda_fp16.h>
#include <cstdint>
#include <math.h>

#define BATCH 4
#define SEQ   2048
#define DMODEL 1024
#define NH    8
#define HD    128
#define HDIM  1024

// ---------------------------------------------------------------------------
// Scratch (device globals: allocation-free rule)
// ---------------------------------------------------------------------------
__device__ __half g_q[(size_t)BATCH * NH * SEQ * HD];        // [B,H,T,D]
__device__ __half g_k[(size_t)BATCH * NH * SEQ * HD];
__device__ __half g_v[(size_t)BATCH * NH * HD * SEQ];        // [B,H,D,T]
__device__ __half g_x[(size_t)BATCH * SEQ * DMODEL];
__device__ __half g_wq[(size_t)3 * HDIM * DMODEL];
__device__ __half g_wp[(size_t)DMODEL * HDIM];
__device__ __half g_y[(size_t)BATCH * SEQ * HDIM];
__device__ float  g_trig[(size_t)SEQ * 64];                  // [t][32][{cos,sin}]

// ---------------------------------------------------------------------------
// PTX helpers
// ---------------------------------------------------------------------------
__device__ __forceinline__ uint32_t smem_u32(const void* p) {
    uint32_t a;
    asm("{ .reg .u64 t; cvta.to.shared.u64 t, %1; cvt.u32.u64 %0, t; }"
        : "=r"(a) : "l"(p));
    return a;
}

#define LDMX4(r, addr) \
    asm volatile("ldmatrix.sync.aligned.m8n8.x4.shared.b16 {%0,%1,%2,%3}, [%4];" \
        : "=r"((r)[0]), "=r"((r)[1]), "=r"((r)[2]), "=r"((r)[3]) : "r"(addr))

#define MMA_F16(d, a, b0, b1) \
    asm volatile("mma.sync.aligned.m16n8k16.row.col.f32.f16.f16.f32 " \
        "{%0,%1,%2,%3},{%4,%5,%6,%7},{%8,%9},{%0,%1,%2,%3};" \
        : "+f"((d)[0]), "+f"((d)[1]), "+f"((d)[2]), "+f"((d)[3]) \
        : "r"((a)[0]), "r"((a)[1]), "r"((a)[2]), "r"((a)[3]), "r"(b0), "r"(b1))

#define CP_ASYNC16(dst, src) \
    asm volatile("cp.async.cg.shared.global [%0], [%1], 16;" :: "r"(dst), "l"(src) : "memory")
#define CP_COMMIT() asm volatile("cp.async.commit_group;" ::: "memory")
#define CP_WAIT0()  asm volatile("cp.async.wait_group 0;" ::: "memory")
#define CP_WAIT1()  asm volatile("cp.async.wait_group 1;" ::: "memory")
#define CP_WAIT2()  asm volatile("cp.async.wait_group 2;" ::: "memory")

__device__ __forceinline__ uint32_t packh(float e0, float e1) {
    __half2 h = __floats2half2_rn(e0, e1);
    return *reinterpret_cast<uint32_t*>(&h);
}

// ---------------------------------------------------------------------------
// conv: fp32 -> fp16; trig table precompute
// ---------------------------------------------------------------------------
__global__ __launch_bounds__(256) void conv_kernel(
    const float* __restrict__ src, __half* __restrict__ dst, int n4)
{
    int i = blockIdx.x * 256 + threadIdx.x;
    if (i < n4) {
        float4 v = ((const float4*)src)[i];
        ((uint2*)dst)[i] = make_uint2(packh(v.x, v.y), packh(v.z, v.w));
    }
}

__global__ __launch_bounds__(32) void trig_kernel(float* __restrict__ tg)
{
    const int t = blockIdx.x, i = threadIdx.x;
    const float xi = (float)i / 31.0f;
    const float f = (float)exp2(-10.0 * (double)xi);
    const float th = (float)t * f;
    tg[t * 64 + i * 2]     = cosf(th);
    tg[t * 64 + i * 2 + 1] = sinf(th);
}

// ===========================================================================
// fp16 GEMM: C[M,N](fp32) = A[M,K] @ B[N,K]^T. CTA 256x128, 512 thr,
// 4-stage cp.async. fused=1: qkv epilogue (RMS+RoPE+v-mix+layout).
// ===========================================================================
#define GA_PART  20480
#define GB_PART  10240
#define G_STAGE  (GA_PART + GB_PART)              // 30720
#define G_SMEM   204800                           // epilogue tile needs 201728

__global__ __launch_bounds__(512, 1) void gemm_f16(
    const __half* __restrict__ A, const __half* __restrict__ B,
    float* __restrict__ C, int Kd, int Nd, int fused,
    __half* __restrict__ Qg, __half* __restrict__ Kg, __half* __restrict__ Vg,
    const float* __restrict__ ve, const float* __restrict__ lam,
    const float* __restrict__ trig_g)
{
    extern __shared__ char smem[];
    const uint32_t sb = smem_u32(smem);
    const int tid = threadIdx.x;
    const int wid = tid >> 5, lane = tid & 31;
    const int wm = wid >> 2, wn = wid & 3;
    const int m0 = blockIdx.y * 256, n0 = blockIdx.x * 128;
    const int nch = Kd / 32;

    auto load_stage = [&](int c) {
        const uint32_t st = sb + (c & 3) * G_STAGE;
        const __half* pA = A + (size_t)m0 * Kd + c * 32;
        const __half* pB = B + (size_t)n0 * Kd + c * 32;
#pragma unroll
        for (int i = 0; i < 2; i++) {
            const int cc = i * 512 + tid;
            const int row = cc >> 2, col = cc & 3;
            CP_ASYNC16(st + row * 80 + col * 16, pA + (size_t)row * Kd + col * 8);
        }
        {
            const int row = tid >> 2, col = tid & 3;
            CP_ASYNC16(st + GA_PART + row * 80 + col * 16, pB + (size_t)row * Kd + col * 8);
        }
    };

    float acc[4][4][4];
#pragma unroll
    for (int i = 0; i < 4; i++)
#pragma unroll
        for (int j = 0; j < 4; j++)
#pragma unroll
            for (int e = 0; e < 4; e++) acc[i][j][e] = 0.f;

    auto compute = [&](int s) {
        const uint32_t st = sb + s * G_STAGE;
        const uint32_t lrow = (lane & 15);
        const uint32_t lcol = (lane >> 4) * 16;
#pragma unroll
        for (int k16 = 0; k16 < 2; k16++) {
            const uint32_t kb2 = k16 * 32;
            uint32_t a_[4][4];
#pragma unroll
            for (int i = 0; i < 4; i++)
                LDMX4(a_[i], st + (wm * 64 + i * 16 + lrow) * 80 + kb2 + lcol);
            uint32_t b_[4][2];
#pragma unroll
            for (int jj = 0; jj < 2; jj++) {
                uint32_t r[4];
                LDMX4(r, st + GA_PART + (wn * 32 + jj * 16 + lrow) * 80 + kb2 + lcol);
                b_[2 * jj][0] = r[0]; b_[2 * jj][1] = r[2];
                b_[2 * jj + 1][0] = r[1]; b_[2 * jj + 1][1] = r[3];
            }
#pragma unroll
            for (int i = 0; i < 4; i++)
#pragma unroll
                for (int j = 0; j < 4; j++)
                    MMA_F16(acc[i][j], a_[i], b_[j][0], b_[j][1]);
        }
    };

    load_stage(0); CP_COMMIT();
    load_stage(1); CP_COMMIT();
    load_stage(2); CP_COMMIT();
    for (int c = 0; c < nch; c++) {
        if (c + 2 < nch) CP_WAIT2();
        else if (c + 1 < nch) CP_WAIT1();
        else CP_WAIT0();
        __syncthreads();
        if (c + 3 < nch) { load_stage(c + 3); CP_COMMIT(); }
        compute(c & 3);
    }

    const int r = lane >> 2;
    const int cb = (lane & 3) * 2;

    if (!fused) {
#pragma unroll
        for (int i = 0; i < 4; i++) {
            const int row0 = m0 + wm * 64 + i * 16 + r;
#pragma unroll
            for (int j = 0; j < 4; j++) {
                const int col = n0 + wn * 32 + j * 8 + cb;
                *(float2*)(C + (size_t)row0 * Nd + col) = make_float2(acc[i][j][0], acc[i][j][1]);
                *(float2*)(C + (size_t)(row0 + 8) * Nd + col) = make_float2(acc[i][j][2], acc[i][j][3]);
            }
        }
        return;
    }

    // ======================= fused qkv epilogue ==========================
    float* tile = (float*)smem;              // [256][132]
    float* rsc  = tile + 256 * 132;          // [256]
    float* trig = rsc + 256;                 // [256][32][2]

    __syncthreads();

#pragma unroll
    for (int i = 0; i < 4; i++) {
        const int row = wm * 64 + i * 16 + r;
#pragma unroll
        for (int j = 0; j < 4; j++) {
            const int col = wn * 32 + j * 8 + cb;
            *(float2*)(tile + row * 132 + col) = make_float2(acc[i][j][0], acc[i][j][1]);
            *(float2*)(tile + (row + 8) * 132 + col) = make_float2(acc[i][j][2], acc[i][j][3]);
        }
    }

    const int part = n0 >> 7;        // 0..23
    const int kind = part >> 3;      // 0=q 1=k 2=v
    const int h = part & 7;

    if (kind < 2) {
        __syncthreads();
        {
            const int row = tid >> 1, hs = tid & 1;
            const float* tr = tile + row * 132 + hs * 64;
            float s = 0.f;
#pragma unroll
            for (int k4 = 0; k4 < 16; k4++) {
                float4 v = *(const float4*)(tr + k4 * 4);
                s += v.x * v.x + v.y * v.y + v.z * v.z + v.w * v.w;
            }
            s += __shfl_xor_sync(0xffffffffu, s, 1);
            if (hs == 0)
                rsc[row] = rsqrtf(s * (1.0f / 128.0f) + 1.1920929e-7f);
        }
        // copy precomputed trig rows into smem
        for (int e = tid; e < 8192; e += 512) {
            const int row = e >> 5, i = e & 31;
            const int t = (m0 + row) & (SEQ - 1);
            ((float2*)trig)[e] = ((const float2*)trig_g)[t * 32 + i];
        }
        __syncthreads();

        const int dd = (tid & 63) * 2;
        const int rg = tid >> 6;
#pragma unroll 4
        for (int stp = 0; stp < 32; stp++) {
            const int row = rg + stp * 8;
            const float sc = rsc[row];
            float out[2];
#pragma unroll
            for (int e = 0; e < 2; e++) {
                const int d = dd + e;
                const float n = tile[row * 132 + d] * sc;
                const int il = d & 63;
                float cth, sth;
                if (il < 32) {
                    cth = trig[(row * 32 + il) * 2];
                    sth = trig[(row * 32 + il) * 2 + 1];
                } else { cth = 1.f; sth = 0.f; }
                const float partner = tile[row * 132 + (d < 64 ? d + 64 : d - 64)] * sc;
                out[e] = (d < 64) ? (n * cth + partner * sth)
                                  : (n * cth - partner * sth);
            }
            const int m = m0 + row;
            const int b = m >> 11, t = m & (SEQ - 1);
            const size_t o = (((size_t)(b * NH + h)) * SEQ + t) * HD + dd;
            if (kind == 0) *(uint32_t*)(Qg + o) = packh(out[0], out[1]);
            else           *(uint32_t*)(Kg + o) = packh(out[0], out[1]);
        }
    } else {
        const float l0 = lam[0], l1 = lam[1];
        __syncthreads();
        for (int e = tid; e < 32768; e += 512) {
            const int row = e >> 7, d = e & 127;
            const int m = m0 + row;
            const float vv = ve[(size_t)m * HDIM + h * HD + d];
            tile[row * 132 + d] = l0 * tile[row * 132 + d] + l1 * vv;
        }
        __syncthreads();
        const int d = tid >> 2;
        const int tq = (tid & 3) * 64;
        const int b = m0 >> 11, tbase = m0 & (SEQ - 1);
        const size_t obase = (((size_t)(b * NH + h)) * HD + d) * SEQ + tbase + tq;
#pragma unroll 8
        for (int k = 0; k < 64; k += 2) {
            const float v0 = tile[(tq + k) * 132 + d];
            const float v1 = tile[(tq + k + 1) * 132 + d];
            *(uint32_t*)(Vg + obase + k) = packh(v0, v1);
        }
    }
}

// ===========================================================================
// Flash attention, single fp16. 128 q-rows/CTA, 8 warps x 16 rows.
// Q resident; K/V 3-stage cp.async.
// ===========================================================================
#define FQ_PART 34816
#define FK_PART 17408
#define FV_PART 18432
#define FSTAGE  (FK_PART + FV_PART)               // 35840
#define F_SMEM  (FQ_PART + 3 * FSTAGE)            // 142336

__global__ __launch_bounds__(256, 1) void flash_mma(
    const __half* __restrict__ Qg, const __half* __restrict__ Kg,
    const __half* __restrict__ Vg, __half* __restrict__ Yg)
{
    extern __shared__ char smem[];
    const uint32_t sbase = smem_u32(smem);
    const int tid = threadIdx.x;
    const int wid = tid >> 5, lane = tid & 31;
    const int qt = gridDim.x - 1 - blockIdx.x;
    const int bh = blockIdx.y;
    const int b = bh >> 3, h = bh & 7;

    const size_t TD = (size_t)SEQ * HD;
    const __half* q_b = Qg + bh * TD;
    const __half* k_b = Kg + bh * TD;
    const __half* v_b = Vg + bh * TD;

#pragma unroll
    for (int i = 0; i < 8; i++) {
        int c = i * 256 + tid;
        int row = c >> 4, col = c & 15;
        CP_ASYNC16(sbase + row * 272 + col * 16,
                   q_b + (size_t)(qt * 128 + row) * 128 + col * 8);
    }
    auto load_kv = [&](int kt, int s) {
        uint32_t kb = sbase + FQ_PART + s * FSTAGE;
#pragma unroll
        for (int i = 0; i < 4; i++) {
            int c = i * 256 + tid;
            int row = c >> 4, col = c & 15;
            CP_ASYNC16(kb + row * 272 + col * 16,
                       k_b + (size_t)(kt * 64 + row) * 128 + col * 8);
        }
#pragma unroll
        for (int i = 0; i < 4; i++) {
            int c = i * 256 + tid;
            int row = c >> 3, col = c & 7;
            CP_ASYNC16(kb + FK_PART + row * 144 + col * 16,
                       v_b + (size_t)row * SEQ + kt * 64 + col * 8);
        }
    };
    const int nkt = 2 * qt + 2;
    load_kv(0, 0);
    CP_COMMIT();
    load_kv(1, 1);
    CP_COMMIT();

    float acc[16][4];
#pragma unroll
    for (int i = 0; i < 16; i++)
#pragma unroll
        for (int e = 0; e < 4; e++) acc[i][e] = 0.f;
    float m_i[2] = {-1e30f, -1e30f};
    float l_i[2] = {0.f, 0.f};

    const uint32_t lrow = lane & 15;
    const uint32_t lcol = (lane >> 4) * 16;
    const float SC = 0.08838834764831845f;

    for (int kt = 0; kt < nkt; kt++) {
        if (kt + 2 < nkt) {
            load_kv(kt + 2, (kt + 2) % 3);
            CP_COMMIT();
            CP_WAIT2();
        } else if (kt + 1 < nkt) {
            CP_WAIT1();
        } else {
            CP_WAIT0();
        }
        __syncthreads();
        const uint32_t kb = sbase + FQ_PART + (kt % 3) * FSTAGE;

        float s[8][4];
#pragma unroll
        for (int j = 0; j < 8; j++)
#pragma unroll
            for (int e = 0; e < 4; e++) s[j][e] = 0.f;

        const uint32_t qrow = sbase + (wid * 16 + lrow) * 272 + lcol;
#pragma unroll
        for (int k16 = 0; k16 < 8; k16++) {
            uint32_t a_[4];
            LDMX4(a_, qrow + k16 * 32);
            uint32_t kf[4][4];
#pragma unroll
            for (int jj = 0; jj < 4; jj++)
                LDMX4(kf[jj], kb + (jj * 16 + lrow) * 272 + lcol + k16 * 32);
#pragma unroll
            for (int jj = 0; jj < 4; jj++) {
                MMA_F16(s[2 * jj], a_, kf[jj][0], kf[jj][2]);
                MMA_F16(s[2 * jj + 1], a_, kf[jj][1], kf[jj][3]);
            }
        }

        const bool need_mask = (kt >= 2 * qt);
#pragma unroll
        for (int hh = 0; hh < 2; hh++) {
            const int rowg = qt * 128 + wid * 16 + (lane >> 2) + hh * 8;
            float mt = -1e30f;
#pragma unroll
            for (int j = 0; j < 8; j++) {
#pragma unroll
                for (int e = 0; e < 2; e++) {
                    float v = s[j][2 * hh + e] * SC;
                    if (need_mask) {
                        int colg = kt * 64 + j * 8 + (lane & 3) * 2 + e;
                        if (colg > rowg) v = -1e30f;
                    }
                    s[j][2 * hh + e] = v;
                    mt = fmaxf(mt, v);
                }
            }
            mt = fmaxf(mt, __shfl_xor_sync(0xffffffffu, mt, 1));
            mt = fmaxf(mt, __shfl_xor_sync(0xffffffffu, mt, 2));
            float mn = fmaxf(m_i[hh], mt);
            float corr = __expf(m_i[hh] - mn);
            m_i[hh] = mn;
            float rs = 0.f;
#pragma unroll
            for (int j = 0; j < 8; j++) {
#pragma unroll
                for (int e = 0; e < 2; e++) {
                    float p = __expf(s[j][2 * hh + e] - mn);
                    s[j][2 * hh + e] = p;
                    rs += p;
                }
            }
            rs += __shfl_xor_sync(0xffffffffu, rs, 1);
            rs += __shfl_xor_sync(0xffffffffu, rs, 2);
            l_i[hh] = l_i[hh] * corr + rs;
#pragma unroll
            for (int ot = 0; ot < 16; ot++) {
                acc[ot][2 * hh] *= corr;
                acc[ot][2 * hh + 1] *= corr;
            }
        }

        const uint32_t vb = kb + FK_PART;
#pragma unroll
        for (int kk = 0; kk < 4; kk++) {
            const int j0 = 2 * kk, j1 = 2 * kk + 1;
            uint32_t p_[4];
            p_[0] = packh(s[j0][0], s[j0][1]);
            p_[1] = packh(s[j0][2], s[j0][3]);
            p_[2] = packh(s[j1][0], s[j1][1]);
            p_[3] = packh(s[j1][2], s[j1][3]);
#pragma unroll
            for (int jp = 0; jp < 4; jp++) {
                const int ja = 2 * jp, jb2 = 2 * jp + 1;
                uint32_t rA[4], rB[4];
                LDMX4(rA, vb + (ja * 16 + lrow) * 144 + kk * 32 + lcol);
                LDMX4(rB, vb + (jb2 * 16 + lrow) * 144 + kk * 32 + lcol);
                MMA_F16(acc[2 * ja], p_, rA[0], rA[2]);
                MMA_F16(acc[2 * ja + 1], p_, rA[1], rA[3]);
                MMA_F16(acc[2 * jb2], p_, rB[0], rB[2]);
                MMA_F16(acc[2 * jb2 + 1], p_, rB[1], rB[3]);
            }
        }
        __syncthreads();
    }

    const float inv0 = 1.f / l_i[0];
    const float inv1 = 1.f / l_i[1];
    const int r0 = qt * 128 + wid * 16 + (lane >> 2);
    const int cb = (lane & 3) * 2;
#pragma unroll
    for (int ot = 0; ot < 16; ot++) {
        const int d = ot * 8 + cb;
        size_t o0 = ((size_t)b * SEQ + r0) * HDIM + h * HD + d;
        size_t o1 = o0 + (size_t)8 * HDIM;
        *(uint32_t*)(Yg + o0) = packh(acc[ot][0] * inv0, acc[ot][1] * inv0);
        *(uint32_t*)(Yg + o1) = packh(acc[ot][2] * inv1, acc[ot][3] * inv1);
    }
}

// ---------------------------------------------------------------------------
extern "C" void kernel_launch(void* const* d_in, const int* in_sizes, int n_in,
                              void* d_out, int out_size)
{
    const float* x        = (const float*)d_in[0];
    const float* ve       = (const float*)d_in[1];
    const float* qkv_w    = (const float*)d_in[2];   // [3*HDIM, DIM]
    const float* lambdas  = (const float*)d_in[3];
    const float* c_proj_w = (const float*)d_in[4];   // [DIM, HDIM]
    float* out = (float*)d_out;

    __half *Q, *K, *V, *X, *Wq, *Wp, *Y;
    float* Tg;
    cudaGetSymbolAddress((void**)&Q, g_q);
    cudaGetSymbolAddress((void**)&K, g_k);
    cudaGetSymbolAddress((void**)&V, g_v);
    cudaGetSymbolAddress((void**)&X, g_x);
    cudaGetSymbolAddress((void**)&Wq, g_wq);
    cudaGetSymbolAddress((void**)&Wp, g_wp);
    cudaGetSymbolAddress((void**)&Y, g_y);
    cudaGetSymbolAddress((void**)&Tg, g_trig);

    cudaFuncSetAttribute(gemm_f16, cudaFuncAttributeMaxDynamicSharedMemorySize, G_SMEM);
    cudaFuncSetAttribute(flash_mma, cudaFuncAttributeMaxDynamicSharedMemorySize, F_SMEM);

    // 0) operand conversion + trig table
    {
        int n4 = BATCH * SEQ * DMODEL / 4;
        conv_kernel<<<(n4 + 255) / 256, 256>>>(x, X, n4);
        n4 = 3 * HDIM * DMODEL / 4;
        conv_kernel<<<(n4 + 255) / 256, 256>>>(qkv_w, Wq, n4);
        n4 = DMODEL * HDIM / 4;
        conv_kernel<<<(n4 + 255) / 256, 256>>>(c_proj_w, Wp, n4);
        trig_kernel<<<SEQ, 32>>>(Tg);
    }

    // 1) fused qkv GEMM + rms/rope/v-mix/layout -> Q,K,V
    gemm_f16<<<dim3(3 * HDIM / 128, BATCH * SEQ / 256), 512, G_SMEM>>>(
        X, Wq, nullptr, DMODEL, 3 * HDIM, 1, Q, K, V, ve, lambdas, Tg);

    // 2) flash attention -> Y (fp16)
    flash_mma<<<dim3(SEQ / 128, BATCH * NH), 256, F_SMEM>>>(Q, K, V, Y);

    // 3) out = Y @ c_proj_w^T
    gemm_f16<<<dim3(DMODEL / 128, BATCH * SEQ / 256), 512, G_SMEM>>>(
        Y, Wp, out, HDIM, DMODEL, 0,
        nullptr, nullptr, nullptr, nullptr, nullptr, nullptr);
}